// round 4
// baseline (speedup 1.0000x reference)
#include <cuda_runtime.h>
#include <cuda_fp16.h>
#include <cstdint>

// Problem constants
#define BB 8
#define NN 2048
#define TT 12
#define DD 256
#define HH 8
#define DKK 32
#define MM 8

#define ROWS (BB*NN*TT)     // 196608
#define BNTOT (BB*NN)       // 16384
#define XELEMS ((size_t)ROWS * 256)

// Scratch (device globals: allocation-free kernel_launch)
__device__ float  g_qkv[(size_t)ROWS * 768];   // QKV projection output (fp32)
__device__ float  g_fc [(size_t)ROWS * 256];   // fc output (pre-residual)
__device__ __half g_xh [XELEMS];               // x split hi
__device__ __half g_xl [XELEMS];               // x split lo
__device__ __half g_ah [XELEMS];               // attn out split hi
__device__ __half g_al [XELEMS];               // attn out split lo
__device__ __half g_wh [1024 * 256];           // weights hi: [Wq;Wk;Wv;fc]
__device__ __half g_wl [1024 * 256];           // weights lo
__device__ float  g_bias[1024];                // [bq;bk;bv;fcb]

// ---------------------------------------------------------------------------
// Split-conversion helpers
// ---------------------------------------------------------------------------
__device__ __forceinline__ uint32_t pack2(__half a, __half b) {
    __half2 h = __halves2half2(a, b);
    return *(uint32_t*)&h;
}

__global__ __launch_bounds__(256) void cvt_split(
    const float* __restrict__ in, __half* __restrict__ hi, __half* __restrict__ lo, size_t n)
{
    size_t i = ((size_t)blockIdx.x * blockDim.x + threadIdx.x) * 4;
    if (i >= n) return;
    float4 v = *(const float4*)(in + i);
    __half h0 = __float2half_rn(v.x), h1 = __float2half_rn(v.y);
    __half h2 = __float2half_rn(v.z), h3 = __float2half_rn(v.w);
    *(uint2*)(hi + i) = make_uint2(pack2(h0, h1), pack2(h2, h3));
    *(uint2*)(lo + i) = make_uint2(
        pack2(__float2half_rn(v.x - __half2float(h0)), __float2half_rn(v.y - __half2float(h1))),
        pack2(__float2half_rn(v.z - __half2float(h2)), __float2half_rn(v.w - __half2float(h3))));
}

// weights: 4 matrices of 256x256 -> concatenated 1024x256 hi/lo; bias concat
__global__ __launch_bounds__(256) void cvt_weights(
    const float* __restrict__ Wq, const float* __restrict__ Wk,
    const float* __restrict__ Wv, const float* __restrict__ Wf,
    const float* __restrict__ bq, const float* __restrict__ bk,
    const float* __restrict__ bv, const float* __restrict__ bf)
{
    size_t i = ((size_t)blockIdx.x * blockDim.x + threadIdx.x) * 4;
    if (i < 4 * 65536) {
        int mat = (int)(i >> 16);
        size_t off = i & 65535;
        const float* W = (mat == 0) ? Wq : (mat == 1 ? Wk : (mat == 2 ? Wv : Wf));
        float4 v = *(const float4*)(W + off);
        __half h0 = __float2half_rn(v.x), h1 = __float2half_rn(v.y);
        __half h2 = __float2half_rn(v.z), h3 = __float2half_rn(v.w);
        *(uint2*)(g_wh + i) = make_uint2(pack2(h0, h1), pack2(h2, h3));
        *(uint2*)(g_wl + i) = make_uint2(
            pack2(__float2half_rn(v.x - __half2float(h0)), __float2half_rn(v.y - __half2float(h1))),
            pack2(__float2half_rn(v.z - __half2float(h2)), __float2half_rn(v.w - __half2float(h3))));
    }
    int t = blockIdx.x * blockDim.x + threadIdx.x;
    if (t < 256)        g_bias[t]       = bq[t];
    else if (t < 512)   g_bias[t]       = bk[t - 256];
    else if (t < 768)   g_bias[t]       = bv[t - 512];
    else if (t < 1024)  g_bias[t]       = bf[t - 768];
}

// ---------------------------------------------------------------------------
// Pure-f16 tensor-core GEMM with 3-term split accumulate.
// Block 128x128, 4 warps (warp tile 64x64), BK=32, cp.async double buffered.
// A: [M][256] hi/lo planes; W: [n][256] hi/lo planes (row base = n0+row).
// ---------------------------------------------------------------------------
#define ASTR 40          // halves per smem row (32 data + 8 pad): conflict-free + 16B aligned
#define STAGEH (128*ASTR) // halves per plane-buffer

__device__ __forceinline__ void ldsm4(uint32_t* r, const __half* p) {
    uint32_t a = (uint32_t)__cvta_generic_to_shared(p);
    asm volatile("ldmatrix.sync.aligned.m8n8.x4.shared.b16 {%0,%1,%2,%3}, [%4];"
                 : "=r"(r[0]), "=r"(r[1]), "=r"(r[2]), "=r"(r[3]) : "r"(a));
}
__device__ __forceinline__ void mma16816(float* d, const uint32_t* a, const uint32_t* b) {
    asm volatile("mma.sync.aligned.m16n8k16.row.col.f32.f16.f16.f32 "
        "{%0,%1,%2,%3}, {%4,%5,%6,%7}, {%8,%9}, {%0,%1,%2,%3};"
        : "+f"(d[0]), "+f"(d[1]), "+f"(d[2]), "+f"(d[3])
        : "r"(a[0]), "r"(a[1]), "r"(a[2]), "r"(a[3]), "r"(b[0]), "r"(b[1]));
}
__device__ __forceinline__ void cpa16(__half* dst, const __half* src) {
    uint32_t d = (uint32_t)__cvta_generic_to_shared(dst);
    asm volatile("cp.async.cg.shared.global [%0], [%1], 16;" :: "r"(d), "l"(src));
}

__global__ __launch_bounds__(128) void gemm_f16d(
    const __half* __restrict__ Ah, const __half* __restrict__ Al,
    const __half* __restrict__ Wh, const __half* __restrict__ Wl,
    const float* __restrict__ bias,
    float* __restrict__ C, int ldc)
{
    extern __shared__ __half sm[];
    __half* sAh = sm;
    __half* sAl = sm + 2 * STAGEH;
    __half* sBh = sm + 4 * STAGEH;
    __half* sBl = sm + 6 * STAGEH;

    const int tid  = threadIdx.x;
    const int m0   = blockIdx.y * 128;
    const int n0   = blockIdx.x * 128;
    const int wid  = tid >> 5;
    const int lane = tid & 31;
    const int WM = (wid & 1) * 64;
    const int WN = (wid >> 1) * 64;

    float acc[4][8][4];
    #pragma unroll
    for (int i = 0; i < 4; i++)
        #pragma unroll
        for (int j = 0; j < 8; j++)
            #pragma unroll
            for (int e = 0; e < 4; e++) acc[i][j][e] = 0.f;

    const size_t arow = (size_t)(m0 + tid) * 256;
    const size_t brow = (size_t)(n0 + tid) * 256;

    // stage loader: 16B chunks, one row per thread
    auto load_stage = [&](int s, int buf) {
        const int k0 = s * 32;
        __half* dA_h = sAh + buf * STAGEH + tid * ASTR;
        __half* dA_l = sAl + buf * STAGEH + tid * ASTR;
        __half* dB_h = sBh + buf * STAGEH + tid * ASTR;
        __half* dB_l = sBl + buf * STAGEH + tid * ASTR;
        #pragma unroll
        for (int c = 0; c < 4; c++) {
            cpa16(dA_h + c * 8, Ah + arow + k0 + c * 8);
            cpa16(dA_l + c * 8, Al + arow + k0 + c * 8);
            cpa16(dB_h + c * 8, Wh + brow + k0 + c * 8);
            cpa16(dB_l + c * 8, Wl + brow + k0 + c * 8);
        }
    };

    load_stage(0, 0);
    asm volatile("cp.async.commit_group;");

    int buf = 0;
    for (int s = 0; s < 8; s++) {
        if (s < 7) {
            load_stage(s + 1, buf ^ 1);
            asm volatile("cp.async.commit_group;");
            asm volatile("cp.async.wait_group 1;");
        } else {
            asm volatile("cp.async.wait_group 0;");
        }
        __syncthreads();

        const __half* bAh = sAh + buf * STAGEH;
        const __half* bAl = sAl + buf * STAGEH;
        const __half* bBh = sBh + buf * STAGEH;
        const __half* bBl = sBl + buf * STAGEH;

        #pragma unroll
        for (int ki = 0; ki < 2; ki++) {
            uint32_t ah[4][4], al[4][4], bh[4][4], bl[4][4];
            const int ar = WM + (lane & 15);
            const int ac = ki * 16 + ((lane & 16) >> 1);
            #pragma unroll
            for (int i = 0; i < 4; i++) {
                ldsm4(ah[i], bAh + (ar + i * 16) * ASTR + ac);
                ldsm4(al[i], bAl + (ar + i * 16) * ASTR + ac);
            }
            const int br = WN + (lane & 7) + ((lane & 16) >> 1);
            const int bc = ki * 16 + (lane & 8);
            #pragma unroll
            for (int j = 0; j < 4; j++) {
                ldsm4(bh[j], bBh + (br + j * 16) * ASTR + bc);
                ldsm4(bl[j], bBl + (br + j * 16) * ASTR + bc);
            }
            #pragma unroll
            for (int i = 0; i < 4; i++) {
                #pragma unroll
                for (int jj = 0; jj < 8; jj++) {
                    const uint32_t* bhp = &bh[jj >> 1][(jj & 1) * 2];
                    const uint32_t* blp = &bl[jj >> 1][(jj & 1) * 2];
                    mma16816(acc[i][jj], ah[i], bhp);
                    mma16816(acc[i][jj], al[i], bhp);
                    mma16816(acc[i][jj], ah[i], blp);
                }
            }
        }
        __syncthreads();
        buf ^= 1;
    }

    // epilogue: bias + fp32 store
    const int cr = lane >> 2;
    const int cc = (lane & 3) * 2;
    #pragma unroll
    for (int jj = 0; jj < 8; jj++) {
        int coll = WN + jj * 8 + cc;
        float bv0 = bias[n0 + coll];
        float bv1 = bias[n0 + coll + 1];
        #pragma unroll
        for (int i = 0; i < 4; i++) {
            int r0 = m0 + WM + i * 16 + cr;
            *(float2*)(C + (size_t)r0 * ldc + n0 + coll) =
                make_float2(acc[i][jj][0] + bv0, acc[i][jj][1] + bv1);
            *(float2*)(C + (size_t)(r0 + 8) * ldc + n0 + coll) =
                make_float2(acc[i][jj][2] + bv0, acc[i][jj][3] + bv1);
        }
    }
}

// ---------------------------------------------------------------------------
// Attention: one block per (b,n); warp = head. Writes hi/lo fp16 split output.
// ---------------------------------------------------------------------------
__global__ __launch_bounds__(256) void attn_kernel(
    const float* __restrict__ memk,
    const float* __restrict__ memv,
    const float* __restrict__ alpha,
    const float* __restrict__ QKV,
    __half* __restrict__ Oh, __half* __restrict__ Ol)
{
    __shared__ float sQ[HH][TT][33];
    __shared__ float sK[HH][TT][33];
    __shared__ float sV[HH][TT][33];
    __shared__ float sS[HH][TT][13];
    __shared__ float sL[HH][TT][8];

    const int bn   = blockIdx.x;
    const int h    = threadIdx.x >> 5;
    const int lane = threadIdx.x & 31;
    const size_t rb = (size_t)bn * TT * 768;
    const float scale = 0.1767766952966369f;

    #pragma unroll
    for (int t = 0; t < TT; t++) {
        sQ[h][t][lane] = QKV[rb + (size_t)t * 768 +       h * 32 + lane];
        sK[h][t][lane] = QKV[rb + (size_t)t * 768 + 256 + h * 32 + lane];
        sV[h][t][lane] = QKV[rb + (size_t)t * 768 + 512 + h * 32 + lane];
    }
    __syncwarp();

    for (int p = lane; p < 144; p += 32) {
        int t = p / 12, s = p - t * 12;
        if (s <= t) {
            float a = 0.f;
            #pragma unroll
            for (int k = 0; k < 32; k++) a += sQ[h][t][k] * sK[h][s][k];
            sS[h][t][s] = a * scale;
        }
    }
    for (int p = lane; p < 96; p += 32) {
        int t = p >> 3, m = p & 7;
        const float* mk = memk + ((h << 3) + m) * 32;
        float a = 0.f;
        #pragma unroll
        for (int k = 0; k < 32; k++) a += sQ[h][t][k] * mk[k];
        sL[h][t][m] = a * scale;
    }
    __syncwarp();

    if (lane < TT) {
        int t = lane;
        float mx = -1e30f;
        for (int s = 0; s <= t; s++) mx = fmaxf(mx, sS[h][t][s]);
        float sum = 0.f;
        for (int s = 0; s <= t; s++) { float e = __expf(sS[h][t][s] - mx); sS[h][t][s] = e; sum += e; }
        float inv = 1.f / sum;
        for (int s = 0; s <= t; s++) sS[h][t][s] *= inv;

        mx = -1e30f;
        #pragma unroll
        for (int m = 0; m < 8; m++) mx = fmaxf(mx, sL[h][t][m]);
        sum = 0.f;
        #pragma unroll
        for (int m = 0; m < 8; m++) { float e = __expf(sL[h][t][m] - mx); sL[h][t][m] = e; sum += e; }
        inv = 1.f / sum;
        #pragma unroll
        for (int m = 0; m < 8; m++) sL[h][t][m] *= inv;
    }
    __syncwarp();

    const float wl = 1.f / (1.f + __expf(-alpha[0]));
    const float wt = 1.f - wl;

    #pragma unroll
    for (int t = 0; t < TT; t++) {
        float ot = 0.f;
        for (int s = 0; s <= t; s++) ot += sS[h][t][s] * sV[h][s][lane];
        float ol = 0.f;
        #pragma unroll
        for (int m = 0; m < 8; m++) ol += sL[h][t][m] * memv[((h << 3) + m) * 32 + lane];
        float v = ot * wt + ol * wl;
        size_t oi = (size_t)bn * TT * 256 + (size_t)t * 256 + h * 32 + lane;
        __half hi = __float2half_rn(v);
        Oh[oi] = hi;
        Ol[oi] = __float2half_rn(v - __half2float(hi));
    }
}

// ---------------------------------------------------------------------------
// Residual + LayerNorm: one warp per row of 256.
// ---------------------------------------------------------------------------
__global__ __launch_bounds__(256) void ln_kernel(
    const float* __restrict__ Y, const float* __restrict__ X,
    const float* __restrict__ gamma, const float* __restrict__ beta,
    float* __restrict__ out)
{
    int gw   = (blockIdx.x * blockDim.x + threadIdx.x) >> 5;
    int lane = threadIdx.x & 31;
    if (gw >= ROWS) return;
    size_t base = (size_t)gw * 256 + lane * 8;

    float4 y1 = *(const float4*)(Y + base);
    float4 y2 = *(const float4*)(Y + base + 4);
    float4 x1 = *(const float4*)(X + base);
    float4 x2 = *(const float4*)(X + base + 4);
    float hh[8] = { y1.x + x1.x, y1.y + x1.y, y1.z + x1.z, y1.w + x1.w,
                    y2.x + x2.x, y2.y + x2.y, y2.z + x2.z, y2.w + x2.w };

    float s = 0.f, sq = 0.f;
    #pragma unroll
    for (int i = 0; i < 8; i++) { s += hh[i]; sq += hh[i] * hh[i]; }
    #pragma unroll
    for (int off = 16; off; off >>= 1) {
        s  += __shfl_xor_sync(0xFFFFFFFFu, s,  off);
        sq += __shfl_xor_sync(0xFFFFFFFFu, sq, off);
    }
    float mu  = s * (1.f / 256.f);
    float var = sq * (1.f / 256.f) - mu * mu;
    float rs  = rsqrtf(var + 1e-5f);

    float4 g1 = *(const float4*)(gamma + lane * 8);
    float4 g2 = *(const float4*)(gamma + lane * 8 + 4);
    float4 be1 = *(const float4*)(beta + lane * 8);
    float4 be2 = *(const float4*)(beta + lane * 8 + 4);

    float4 o1 = make_float4((hh[0] - mu) * rs * g1.x + be1.x,
                            (hh[1] - mu) * rs * g1.y + be1.y,
                            (hh[2] - mu) * rs * g1.z + be1.z,
                            (hh[3] - mu) * rs * g1.w + be1.w);
    float4 o2 = make_float4((hh[4] - mu) * rs * g2.x + be2.x,
                            (hh[5] - mu) * rs * g2.y + be2.y,
                            (hh[6] - mu) * rs * g2.z + be2.z,
                            (hh[7] - mu) * rs * g2.w + be2.w);
    *(float4*)(out + base)     = o1;
    *(float4*)(out + base + 4) = o2;
}

// ---------------------------------------------------------------------------
extern "C" void kernel_launch(void* const* d_in, const int* in_sizes, int n_in,
                              void* d_out, int out_size)
{
    const float* x     = (const float*)d_in[0];
    const float* Wq    = (const float*)d_in[1];
    const float* bq    = (const float*)d_in[2];
    const float* Wk    = (const float*)d_in[3];
    const float* bk    = (const float*)d_in[4];
    const float* Wv    = (const float*)d_in[5];
    const float* bv    = (const float*)d_in[6];
    const float* memk  = (const float*)d_in[7];
    const float* memv  = (const float*)d_in[8];
    const float* fcw   = (const float*)d_in[9];
    const float* fcb   = (const float*)d_in[10];
    const float* gamma = (const float*)d_in[11];
    const float* beta  = (const float*)d_in[12];
    const float* alpha = (const float*)d_in[13];
    float* out = (float*)d_out;

    float *qkv, *fc, *bias;
    __half *xh, *xl, *ah, *al, *wh, *wlp;
    cudaGetSymbolAddress((void**)&qkv, g_qkv);
    cudaGetSymbolAddress((void**)&fc,  g_fc);
    cudaGetSymbolAddress((void**)&xh,  g_xh);
    cudaGetSymbolAddress((void**)&xl,  g_xl);
    cudaGetSymbolAddress((void**)&ah,  g_ah);
    cudaGetSymbolAddress((void**)&al,  g_al);
    cudaGetSymbolAddress((void**)&wh,  g_wh);
    cudaGetSymbolAddress((void**)&wlp, g_wl);
    cudaGetSymbolAddress((void**)&bias, g_bias);

    static bool attr_set = false;
    if (!attr_set) {
        cudaFuncSetAttribute(gemm_f16d, cudaFuncAttributeMaxDynamicSharedMemorySize, 8 * STAGEH * 2);
        attr_set = true;
    }
    const int smem = 8 * STAGEH * 2;  // 81920 bytes

    // 0) split-convert inputs
    cvt_split<<<(unsigned)(XELEMS / 4 / 256), 256>>>(x, xh, xl, XELEMS);
    cvt_weights<<<256, 256>>>(Wq, Wk, Wv, fcw, bq, bk, bv, fcb);

    // 1) fused QKV projection
    {
        dim3 grid(6, ROWS / 128);
        gemm_f16d<<<grid, 128, smem>>>(xh, xl, wh, wlp, bias, qkv, 768);
    }
    // 2) attention per (b,n) -> hi/lo split output
    attn_kernel<<<BNTOT, 256>>>(memk, memv, alpha, qkv, ah, al);

    // 3) FC projection
    {
        dim3 grid(2, ROWS / 128);
        gemm_f16d<<<grid, 128, smem>>>(ah, al, wh + 768 * 256, wlp + 768 * 256,
                                       bias + 768, fc, 256);
    }
    // 4) residual + LayerNorm
    ln_kernel<<<(ROWS * 32 + 255) / 256, 256>>>(fc, x, gamma, beta, out);
}

// round 5
// speedup vs baseline: 1.0211x; 1.0211x over previous
#include <cuda_runtime.h>
#include <cuda_fp16.h>
#include <cstdint>

// Problem constants
#define BB 8
#define NN 2048
#define TT 12
#define DD 256
#define HH 8
#define DKK 32
#define MM 8

#define ROWS (BB*NN*TT)     // 196608
#define BNTOT (BB*NN)       // 16384
#define XELEMS ((size_t)ROWS * 256)

// Scratch (device globals: allocation-free kernel_launch)
__device__ float  g_qkv[(size_t)ROWS * 768];   // QKV projection output (fp32)
__device__ float  g_fc [(size_t)ROWS * 256];   // fc output (pre-residual)
__device__ __half g_xh [XELEMS];               // x split hi
__device__ __half g_xl [XELEMS];               // x split lo
__device__ __half g_ah [XELEMS];               // attn out split hi
__device__ __half g_al [XELEMS];               // attn out split lo
__device__ __half g_wh [1024 * 256];           // weights hi: [Wq;Wk;Wv;fc]
__device__ __half g_wl [1024 * 256];           // weights lo
__device__ float  g_bias[1024];                // [bq;bk;bv;fcb]

// ---------------------------------------------------------------------------
// Split-conversion helpers
// ---------------------------------------------------------------------------
__device__ __forceinline__ uint32_t pack2(__half a, __half b) {
    __half2 h = __halves2half2(a, b);
    return *(uint32_t*)&h;
}

__global__ __launch_bounds__(256) void cvt_split(
    const float* __restrict__ in, __half* __restrict__ hi, __half* __restrict__ lo, size_t n)
{
    size_t i = ((size_t)blockIdx.x * blockDim.x + threadIdx.x) * 4;
    if (i >= n) return;
    float4 v = *(const float4*)(in + i);
    __half h0 = __float2half_rn(v.x), h1 = __float2half_rn(v.y);
    __half h2 = __float2half_rn(v.z), h3 = __float2half_rn(v.w);
    *(uint2*)(hi + i) = make_uint2(pack2(h0, h1), pack2(h2, h3));
    *(uint2*)(lo + i) = make_uint2(
        pack2(__float2half_rn(v.x - __half2float(h0)), __float2half_rn(v.y - __half2float(h1))),
        pack2(__float2half_rn(v.z - __half2float(h2)), __float2half_rn(v.w - __half2float(h3))));
}

__global__ __launch_bounds__(256) void cvt_weights(
    const float* __restrict__ Wq, const float* __restrict__ Wk,
    const float* __restrict__ Wv, const float* __restrict__ Wf,
    const float* __restrict__ bq, const float* __restrict__ bk,
    const float* __restrict__ bv, const float* __restrict__ bf)
{
    size_t i = ((size_t)blockIdx.x * blockDim.x + threadIdx.x) * 4;
    if (i < 4 * 65536) {
        int mat = (int)(i >> 16);
        size_t off = i & 65535;
        const float* W = (mat == 0) ? Wq : (mat == 1 ? Wk : (mat == 2 ? Wv : Wf));
        float4 v = *(const float4*)(W + off);
        __half h0 = __float2half_rn(v.x), h1 = __float2half_rn(v.y);
        __half h2 = __float2half_rn(v.z), h3 = __float2half_rn(v.w);
        *(uint2*)(g_wh + i) = make_uint2(pack2(h0, h1), pack2(h2, h3));
        *(uint2*)(g_wl + i) = make_uint2(
            pack2(__float2half_rn(v.x - __half2float(h0)), __float2half_rn(v.y - __half2float(h1))),
            pack2(__float2half_rn(v.z - __half2float(h2)), __float2half_rn(v.w - __half2float(h3))));
    }
    int t = blockIdx.x * blockDim.x + threadIdx.x;
    if (t < 256)        g_bias[t] = bq[t];
    else if (t < 512)   g_bias[t] = bk[t - 256];
    else if (t < 768)   g_bias[t] = bv[t - 512];
    else if (t < 1024)  g_bias[t] = bf[t - 768];
}

// ---------------------------------------------------------------------------
// Tensor-core GEMM, pre-split fp16 planes, 3-term accumulate.
// Block 128x128, 256 threads, 8 warps (2m x 4n), warp tile 64x32, BK=16,
// cp.async double-buffered. (Compute shape identical to verified R3 kernel.)
// ---------------------------------------------------------------------------
#define ASTR 24              // halves per smem row (16 data + 8 pad)
#define STG  (128 * ASTR)    // halves per array-stage (6 KB)

__device__ __forceinline__ void ldsm4(uint32_t* r, const __half* p) {
    uint32_t a = (uint32_t)__cvta_generic_to_shared(p);
    asm volatile("ldmatrix.sync.aligned.m8n8.x4.shared.b16 {%0,%1,%2,%3}, [%4];"
                 : "=r"(r[0]), "=r"(r[1]), "=r"(r[2]), "=r"(r[3]) : "r"(a));
}
__device__ __forceinline__ void mma16816(float* d, const uint32_t* a, const uint32_t* b) {
    asm volatile("mma.sync.aligned.m16n8k16.row.col.f32.f16.f16.f32 "
        "{%0,%1,%2,%3}, {%4,%5,%6,%7}, {%8,%9}, {%0,%1,%2,%3};"
        : "+f"(d[0]), "+f"(d[1]), "+f"(d[2]), "+f"(d[3])
        : "r"(a[0]), "r"(a[1]), "r"(a[2]), "r"(a[3]), "r"(b[0]), "r"(b[1]));
}
__device__ __forceinline__ void cpa16(__half* dst, const __half* src) {
    uint32_t d = (uint32_t)__cvta_generic_to_shared(dst);
    asm volatile("cp.async.cg.shared.global [%0], [%1], 16;" :: "r"(d), "l"(src));
}

__global__ __launch_bounds__(256, 2) void gemm_f16s(
    const __half* __restrict__ Ah, const __half* __restrict__ Al,
    const __half* __restrict__ Wh, const __half* __restrict__ Wl,
    const float* __restrict__ bias,
    float* __restrict__ C, int ldc)
{
    extern __shared__ __half sm[];   // [2 buf][4 arrays][STG]  = 48 KB

    const int tid  = threadIdx.x;
    const int m0   = blockIdx.y * 128;
    const int n0   = blockIdx.x * 128;
    const int wid  = tid >> 5;
    const int lane = tid & 31;
    const int WM = (wid & 1) * 64;
    const int WN = (wid >> 1) * 32;

    // loader: one 16B chunk per array per thread per stage
    const int lrow = tid >> 1;             // 0..127
    const int lch  = (tid & 1) * 8;        // halves 0 or 8
    const size_t aoff = (size_t)(m0 + lrow) * 256 + lch;
    const size_t boff = (size_t)(n0 + lrow) * 256 + lch;
    const int sdst = lrow * ASTR + lch;

    float acc[4][4][4];
    #pragma unroll
    for (int i = 0; i < 4; i++)
        #pragma unroll
        for (int j = 0; j < 4; j++)
            #pragma unroll
            for (int e = 0; e < 4; e++) acc[i][j][e] = 0.f;

    auto load_stage = [&](int k0, int buf) {
        __half* b = sm + buf * 4 * STG;
        cpa16(b + 0 * STG + sdst, Ah + aoff + k0);
        cpa16(b + 1 * STG + sdst, Al + aoff + k0);
        cpa16(b + 2 * STG + sdst, Wh + boff + k0);
        cpa16(b + 3 * STG + sdst, Wl + boff + k0);
    };

    load_stage(0, 0);
    asm volatile("cp.async.commit_group;");

    int buf = 0;
    for (int s = 0; s < 16; s++) {
        if (s < 15) {
            load_stage((s + 1) * 16, buf ^ 1);
            asm volatile("cp.async.commit_group;");
            asm volatile("cp.async.wait_group 1;");
        } else {
            asm volatile("cp.async.wait_group 0;");
        }
        __syncthreads();

        const __half* bAh = sm + buf * 4 * STG;
        const __half* bAl = bAh + STG;
        const __half* bBh = bAh + 2 * STG;
        const __half* bBl = bAh + 3 * STG;

        uint32_t ah[4][4], al[4][4], bh[2][4], bl[2][4];
        const int ar = WM + (lane & 15);
        const int ac = (lane & 16) >> 1;       // 0 or 8
        #pragma unroll
        for (int i = 0; i < 4; i++) {
            ldsm4(ah[i], bAh + (ar + i * 16) * ASTR + ac);
            ldsm4(al[i], bAl + (ar + i * 16) * ASTR + ac);
        }
        const int br = WN + (lane & 7) + ((lane & 16) >> 1);
        const int bc = lane & 8;
        #pragma unroll
        for (int j = 0; j < 2; j++) {
            ldsm4(bh[j], bBh + (br + j * 16) * ASTR + bc);
            ldsm4(bl[j], bBl + (br + j * 16) * ASTR + bc);
        }
        #pragma unroll
        for (int i = 0; i < 4; i++) {
            #pragma unroll
            for (int jj = 0; jj < 4; jj++) {
                const uint32_t* bhp = &bh[jj >> 1][(jj & 1) * 2];
                const uint32_t* blp = &bl[jj >> 1][(jj & 1) * 2];
                mma16816(acc[i][jj], ah[i], bhp);
                mma16816(acc[i][jj], al[i], bhp);
                mma16816(acc[i][jj], ah[i], blp);
            }
        }
        __syncthreads();
        buf ^= 1;
    }

    // epilogue: bias + fp32 store
    const int cr = lane >> 2;
    const int cc = (lane & 3) * 2;
    #pragma unroll
    for (int jj = 0; jj < 4; jj++) {
        int coll = WN + jj * 8 + cc;
        float bv0 = bias[n0 + coll];
        float bv1 = bias[n0 + coll + 1];
        #pragma unroll
        for (int i = 0; i < 4; i++) {
            int r0 = m0 + WM + i * 16 + cr;
            *(float2*)(C + (size_t)r0 * ldc + n0 + coll) =
                make_float2(acc[i][jj][0] + bv0, acc[i][jj][1] + bv1);
            *(float2*)(C + (size_t)(r0 + 8) * ldc + n0 + coll) =
                make_float2(acc[i][jj][2] + bv0, acc[i][jj][3] + bv1);
        }
    }
}

// ---------------------------------------------------------------------------
// Attention v2: one block per (b,n); warp = head.
// One (t,s)/(t,m) pair per lane, float4 dot products; V & mem_v in registers.
// ---------------------------------------------------------------------------
__global__ __launch_bounds__(256) void attn2_kernel(
    const float* __restrict__ memk,
    const float* __restrict__ memv,
    const float* __restrict__ alpha,
    const float* __restrict__ QKV,
    __half* __restrict__ Oh, __half* __restrict__ Ol)
{
    __shared__ float sQ[HH][TT][36];
    __shared__ float sK[HH][TT][36];
    __shared__ float sS[HH][TT][13];
    __shared__ float sL[HH][TT][9];

    const int bn   = blockIdx.x;
    const int h    = threadIdx.x >> 5;
    const int lane = threadIdx.x & 31;
    const size_t rb = (size_t)bn * TT * 768;
    const float scale = 0.1767766952966369f;

    float v[TT];
    #pragma unroll
    for (int t = 0; t < TT; t++) {
        sQ[h][t][lane] = QKV[rb + (size_t)t * 768 +       h * 32 + lane];
        sK[h][t][lane] = QKV[rb + (size_t)t * 768 + 256 + h * 32 + lane];
        v[t]           = QKV[rb + (size_t)t * 768 + 512 + h * 32 + lane];
    }
    float mv[MM];
    #pragma unroll
    for (int m = 0; m < MM; m++) mv[m] = memv[((h << 3) + m) * 32 + lane];
    __syncwarp();

    // scores: 78 causal pairs + 96 memory pairs, one per lane per sweep
    for (int i = lane; i < 174; i += 32) {
        if (i < 78) {
            int t = (int)((sqrtf(8.f * i + 1.f) - 1.f) * 0.5f);
            if ((t + 1) * (t + 2) / 2 <= i) t++;
            else if (t * (t + 1) / 2 > i) t--;
            int s = i - t * (t + 1) / 2;
            const float4* q = (const float4*)sQ[h][t];
            const float4* k = (const float4*)sK[h][s];
            float a = 0.f;
            #pragma unroll
            for (int c = 0; c < 8; c++) {
                float4 qa = q[c], ka = k[c];
                a += qa.x * ka.x + qa.y * ka.y + qa.z * ka.z + qa.w * ka.w;
            }
            sS[h][t][s] = a * scale;
        } else {
            int j = i - 78;
            int t = j >> 3, m = j & 7;
            const float4* q = (const float4*)sQ[h][t];
            const float4* k = (const float4*)(memk + ((h << 3) + m) * 32);
            float a = 0.f;
            #pragma unroll
            for (int c = 0; c < 8; c++) {
                float4 qa = q[c], ka = k[c];
                a += qa.x * ka.x + qa.y * ka.y + qa.z * ka.z + qa.w * ka.w;
            }
            sL[h][t][m] = a * scale;
        }
    }
    __syncwarp();

    // per-row softmax (lane t < 12)
    if (lane < TT) {
        int t = lane;
        float mx = -1e30f;
        for (int s = 0; s <= t; s++) mx = fmaxf(mx, sS[h][t][s]);
        float sum = 0.f;
        for (int s = 0; s <= t; s++) { float e = __expf(sS[h][t][s] - mx); sS[h][t][s] = e; sum += e; }
        float inv = 1.f / sum;
        for (int s = 0; s <= t; s++) sS[h][t][s] *= inv;

        mx = -1e30f;
        #pragma unroll
        for (int m = 0; m < MM; m++) mx = fmaxf(mx, sL[h][t][m]);
        sum = 0.f;
        #pragma unroll
        for (int m = 0; m < MM; m++) { float e = __expf(sL[h][t][m] - mx); sL[h][t][m] = e; sum += e; }
        inv = 1.f / sum;
        #pragma unroll
        for (int m = 0; m < MM; m++) sL[h][t][m] *= inv;
    }
    __syncwarp();

    const float wl = 1.f / (1.f + __expf(-alpha[0]));
    const float wt = 1.f - wl;

    #pragma unroll
    for (int t = 0; t < TT; t++) {
        float ot = 0.f;
        for (int s = 0; s <= t; s++) ot += sS[h][t][s] * v[s];      // sS broadcast
        float ol = 0.f;
        #pragma unroll
        for (int m = 0; m < MM; m++) ol += sL[h][t][m] * mv[m];
        float o = ot * wt + ol * wl;
        size_t oi = (size_t)bn * TT * 256 + (size_t)t * 256 + h * 32 + lane;
        __half hi = __float2half_rn(o);
        Oh[oi] = hi;
        Ol[oi] = __float2half_rn(o - __half2float(hi));
    }
}

// ---------------------------------------------------------------------------
// Residual + LayerNorm: one warp per row of 256.
// ---------------------------------------------------------------------------
__global__ __launch_bounds__(256) void ln_kernel(
    const float* __restrict__ Y, const float* __restrict__ X,
    const float* __restrict__ gamma, const float* __restrict__ beta,
    float* __restrict__ out)
{
    int gw   = (blockIdx.x * blockDim.x + threadIdx.x) >> 5;
    int lane = threadIdx.x & 31;
    if (gw >= ROWS) return;
    size_t base = (size_t)gw * 256 + lane * 8;

    float4 y1 = *(const float4*)(Y + base);
    float4 y2 = *(const float4*)(Y + base + 4);
    float4 x1 = *(const float4*)(X + base);
    float4 x2 = *(const float4*)(X + base + 4);
    float hh[8] = { y1.x + x1.x, y1.y + x1.y, y1.z + x1.z, y1.w + x1.w,
                    y2.x + x2.x, y2.y + x2.y, y2.z + x2.z, y2.w + x2.w };

    float s = 0.f, sq = 0.f;
    #pragma unroll
    for (int i = 0; i < 8; i++) { s += hh[i]; sq += hh[i] * hh[i]; }
    #pragma unroll
    for (int off = 16; off; off >>= 1) {
        s  += __shfl_xor_sync(0xFFFFFFFFu, s,  off);
        sq += __shfl_xor_sync(0xFFFFFFFFu, sq, off);
    }
    float mu  = s * (1.f / 256.f);
    float var = sq * (1.f / 256.f) - mu * mu;
    float rs  = rsqrtf(var + 1e-5f);

    float4 g1 = *(const float4*)(gamma + lane * 8);
    float4 g2 = *(const float4*)(gamma + lane * 8 + 4);
    float4 be1 = *(const float4*)(beta + lane * 8);
    float4 be2 = *(const float4*)(beta + lane * 8 + 4);

    float4 o1 = make_float4((hh[0] - mu) * rs * g1.x + be1.x,
                            (hh[1] - mu) * rs * g1.y + be1.y,
                            (hh[2] - mu) * rs * g1.z + be1.z,
                            (hh[3] - mu) * rs * g1.w + be1.w);
    float4 o2 = make_float4((hh[4] - mu) * rs * g2.x + be2.x,
                            (hh[5] - mu) * rs * g2.y + be2.y,
                            (hh[6] - mu) * rs * g2.z + be2.z,
                            (hh[7] - mu) * rs * g2.w + be2.w);
    *(float4*)(out + base)     = o1;
    *(float4*)(out + base + 4) = o2;
}

// ---------------------------------------------------------------------------
extern "C" void kernel_launch(void* const* d_in, const int* in_sizes, int n_in,
                              void* d_out, int out_size)
{
    const float* x     = (const float*)d_in[0];
    const float* Wq    = (const float*)d_in[1];
    const float* bq    = (const float*)d_in[2];
    const float* Wk    = (const float*)d_in[3];
    const float* bk    = (const float*)d_in[4];
    const float* Wv    = (const float*)d_in[5];
    const float* bv    = (const float*)d_in[6];
    const float* memk  = (const float*)d_in[7];
    const float* memv  = (const float*)d_in[8];
    const float* fcw   = (const float*)d_in[9];
    const float* fcb   = (const float*)d_in[10];
    const float* gamma = (const float*)d_in[11];
    const float* beta  = (const float*)d_in[12];
    const float* alpha = (const float*)d_in[13];
    float* out = (float*)d_out;

    float *qkv, *fc, *bias;
    __half *xh, *xl, *ah, *al, *wh, *wlp;
    cudaGetSymbolAddress((void**)&qkv, g_qkv);
    cudaGetSymbolAddress((void**)&fc,  g_fc);
    cudaGetSymbolAddress((void**)&xh,  g_xh);
    cudaGetSymbolAddress((void**)&xl,  g_xl);
    cudaGetSymbolAddress((void**)&ah,  g_ah);
    cudaGetSymbolAddress((void**)&al,  g_al);
    cudaGetSymbolAddress((void**)&wh,  g_wh);
    cudaGetSymbolAddress((void**)&wlp, g_wl);
    cudaGetSymbolAddress((void**)&bias, g_bias);

    const int smem = 2 * 4 * STG * 2;  // 49152 bytes
    cudaFuncSetAttribute(gemm_f16s, cudaFuncAttributeMaxDynamicSharedMemorySize, smem);

    // 0) split-convert inputs
    cvt_split<<<(unsigned)(XELEMS / 4 / 256), 256>>>(x, xh, xl, XELEMS);
    cvt_weights<<<256, 256>>>(Wq, Wk, Wv, fcw, bq, bk, bv, fcb);

    // 1) fused QKV projection
    {
        dim3 grid(6, ROWS / 128);
        gemm_f16s<<<grid, 256, smem>>>(xh, xl, wh, wlp, bias, qkv, 768);
    }
    // 2) attention per (b,n) -> hi/lo split output
    attn2_kernel<<<BNTOT, 256>>>(memk, memv, alpha, qkv, ah, al);

    // 3) FC projection
    {
        dim3 grid(2, ROWS / 128);
        gemm_f16s<<<grid, 256, smem>>>(ah, al, wh + 768 * 256, wlp + 768 * 256,
                                       bias + 768, fc, 256);
    }
    // 4) residual + LayerNorm
    ln_kernel<<<(ROWS * 32 + 255) / 256, 256>>>(fc, x, gamma, beta, out);
}

// round 6
// speedup vs baseline: 1.1502x; 1.1265x over previous
#include <cuda_runtime.h>
#include <cuda_fp16.h>
#include <cstdint>

// Problem constants
#define BB 8
#define NN 2048
#define TT 12
#define DD 256
#define HH 8
#define DKK 32
#define MM 8

#define ROWS (BB*NN*TT)     // 196608
#define BNTOT (BB*NN)       // 16384
#define XELEMS ((size_t)ROWS * 256)

// Scratch (device globals: allocation-free kernel_launch)
__device__ float  g_qkv[(size_t)ROWS * 768];   // QKV projection output (fp32)
__device__ float  g_fc [(size_t)ROWS * 256];   // fc output (pre-residual)
__device__ __half g_xh [XELEMS];               // x split hi
__device__ __half g_xl [XELEMS];               // x split lo
__device__ __half g_ah [XELEMS];               // attn out split hi
__device__ __half g_al [XELEMS];               // attn out split lo
__device__ __half g_wh [1024 * 256];           // weights hi: [Wq;Wk;Wv;fc]
__device__ __half g_wl [1024 * 256];           // weights lo
__device__ float  g_bias[1024];                // [bq;bk;bv;fcb]

// ---------------------------------------------------------------------------
// Split-conversion helpers
// ---------------------------------------------------------------------------
__device__ __forceinline__ uint32_t pack2(__half a, __half b) {
    __half2 h = __halves2half2(a, b);
    return *(uint32_t*)&h;
}

__global__ __launch_bounds__(256) void cvt_split(
    const float* __restrict__ in, __half* __restrict__ hi, __half* __restrict__ lo, size_t n)
{
    size_t i = ((size_t)blockIdx.x * blockDim.x + threadIdx.x) * 4;
    if (i >= n) return;
    float4 v = *(const float4*)(in + i);
    __half h0 = __float2half_rn(v.x), h1 = __float2half_rn(v.y);
    __half h2 = __float2half_rn(v.z), h3 = __float2half_rn(v.w);
    *(uint2*)(hi + i) = make_uint2(pack2(h0, h1), pack2(h2, h3));
    *(uint2*)(lo + i) = make_uint2(
        pack2(__float2half_rn(v.x - __half2float(h0)), __float2half_rn(v.y - __half2float(h1))),
        pack2(__float2half_rn(v.z - __half2float(h2)), __float2half_rn(v.w - __half2float(h3))));
}

__global__ __launch_bounds__(256) void cvt_weights(
    const float* __restrict__ Wq, const float* __restrict__ Wk,
    const float* __restrict__ Wv, const float* __restrict__ Wf,
    const float* __restrict__ bq, const float* __restrict__ bk,
    const float* __restrict__ bv, const float* __restrict__ bf)
{
    size_t i = ((size_t)blockIdx.x * blockDim.x + threadIdx.x) * 4;
    if (i < 4 * 65536) {
        int mat = (int)(i >> 16);
        size_t off = i & 65535;
        const float* W = (mat == 0) ? Wq : (mat == 1 ? Wk : (mat == 2 ? Wv : Wf));
        float4 v = *(const float4*)(W + off);
        __half h0 = __float2half_rn(v.x), h1 = __float2half_rn(v.y);
        __half h2 = __float2half_rn(v.z), h3 = __float2half_rn(v.w);
        *(uint2*)(g_wh + i) = make_uint2(pack2(h0, h1), pack2(h2, h3));
        *(uint2*)(g_wl + i) = make_uint2(
            pack2(__float2half_rn(v.x - __half2float(h0)), __float2half_rn(v.y - __half2float(h1))),
            pack2(__float2half_rn(v.z - __half2float(h2)), __float2half_rn(v.w - __half2float(h3))));
    }
    int t = blockIdx.x * blockDim.x + threadIdx.x;
    if (t < 256)        g_bias[t] = bq[t];
    else if (t < 512)   g_bias[t] = bk[t - 256];
    else if (t < 768)   g_bias[t] = bv[t - 512];
    else if (t < 1024)  g_bias[t] = bf[t - 768];
}

// ---------------------------------------------------------------------------
// Tensor-core GEMM, pre-split fp16 planes, 3-term accumulate.
// Block 128x128, 256 threads, 8 warps (2m x 4n), warp tile 64x32, BK=16.
// 4-stage cp.async ring, ONE __syncthreads per stage.
// ---------------------------------------------------------------------------
#define ASTR 24              // halves per smem row (16 data + 8 pad); 48B row, 16B-aligned
#define STG  (128 * ASTR)    // halves per plane-stage (6 KB)
#define NSTAGE 4

__device__ __forceinline__ void ldsm4(uint32_t* r, const __half* p) {
    uint32_t a = (uint32_t)__cvta_generic_to_shared(p);
    asm volatile("ldmatrix.sync.aligned.m8n8.x4.shared.b16 {%0,%1,%2,%3}, [%4];"
                 : "=r"(r[0]), "=r"(r[1]), "=r"(r[2]), "=r"(r[3]) : "r"(a));
}
__device__ __forceinline__ void mma16816(float* d, const uint32_t* a, const uint32_t* b) {
    asm volatile("mma.sync.aligned.m16n8k16.row.col.f32.f16.f16.f32 "
        "{%0,%1,%2,%3}, {%4,%5,%6,%7}, {%8,%9}, {%0,%1,%2,%3};"
        : "+f"(d[0]), "+f"(d[1]), "+f"(d[2]), "+f"(d[3])
        : "r"(a[0]), "r"(a[1]), "r"(a[2]), "r"(a[3]), "r"(b[0]), "r"(b[1]));
}
__device__ __forceinline__ void cpa16(__half* dst, const __half* src) {
    uint32_t d = (uint32_t)__cvta_generic_to_shared(dst);
    asm volatile("cp.async.cg.shared.global [%0], [%1], 16;" :: "r"(d), "l"(src));
}

__global__ __launch_bounds__(256, 2) void gemm_f16s(
    const __half* __restrict__ Ah, const __half* __restrict__ Al,
    const __half* __restrict__ Wh, const __half* __restrict__ Wl,
    const float* __restrict__ bias,
    float* __restrict__ C, int ldc)
{
    extern __shared__ __half sm[];   // [NSTAGE][4 planes][STG] = 96 KB

    const int tid  = threadIdx.x;
    const int m0   = blockIdx.y * 128;
    const int n0   = blockIdx.x * 128;
    const int wid  = tid >> 5;
    const int lane = tid & 31;
    const int WM = (wid & 1) * 64;
    const int WN = (wid >> 1) * 32;

    const int lrow = tid >> 1;
    const int lch  = (tid & 1) * 8;
    const size_t aoff = (size_t)(m0 + lrow) * 256 + lch;
    const size_t boff = (size_t)(n0 + lrow) * 256 + lch;
    const int sdst = lrow * ASTR + lch;

    float acc[4][4][4];
    #pragma unroll
    for (int i = 0; i < 4; i++)
        #pragma unroll
        for (int j = 0; j < 4; j++)
            #pragma unroll
            for (int e = 0; e < 4; e++) acc[i][j][e] = 0.f;

    auto load_stage = [&](int k0, int buf) {
        __half* b = sm + buf * 4 * STG;
        cpa16(b + 0 * STG + sdst, Ah + aoff + k0);
        cpa16(b + 1 * STG + sdst, Al + aoff + k0);
        cpa16(b + 2 * STG + sdst, Wh + boff + k0);
        cpa16(b + 3 * STG + sdst, Wl + boff + k0);
        asm volatile("cp.async.commit_group;");
    };

    // prologue: 3 stages in flight
    load_stage(0, 0);
    load_stage(16, 1);
    load_stage(32, 2);

    for (int s = 0; s < 16; s++) {
        if (s <= 13)      asm volatile("cp.async.wait_group 2;");
        else if (s == 14) asm volatile("cp.async.wait_group 1;");
        else              asm volatile("cp.async.wait_group 0;");
        __syncthreads();          // stage s ready; prior reads of buf (s&3) finished

        if (s <= 12) load_stage((s + 3) * 16, (s + 3) & 3);

        const __half* bAh = sm + (s & 3) * 4 * STG;
        const __half* bAl = bAh + STG;
        const __half* bBh = bAh + 2 * STG;
        const __half* bBl = bAh + 3 * STG;

        uint32_t ah[4][4], al[4][4], bh[2][4], bl[2][4];
        const int ar = WM + (lane & 15);
        const int ac = (lane & 16) >> 1;
        #pragma unroll
        for (int i = 0; i < 4; i++) {
            ldsm4(ah[i], bAh + (ar + i * 16) * ASTR + ac);
            ldsm4(al[i], bAl + (ar + i * 16) * ASTR + ac);
        }
        const int br = WN + (lane & 7) + ((lane & 16) >> 1);
        const int bc = lane & 8;
        #pragma unroll
        for (int j = 0; j < 2; j++) {
            ldsm4(bh[j], bBh + (br + j * 16) * ASTR + bc);
            ldsm4(bl[j], bBl + (br + j * 16) * ASTR + bc);
        }
        #pragma unroll
        for (int i = 0; i < 4; i++) {
            #pragma unroll
            for (int jj = 0; jj < 4; jj++) {
                const uint32_t* bhp = &bh[jj >> 1][(jj & 1) * 2];
                const uint32_t* blp = &bl[jj >> 1][(jj & 1) * 2];
                mma16816(acc[i][jj], ah[i], bhp);
                mma16816(acc[i][jj], al[i], bhp);
                mma16816(acc[i][jj], ah[i], blp);
            }
        }
    }

    // epilogue: bias + fp32 store
    const int cr = lane >> 2;
    const int cc = (lane & 3) * 2;
    #pragma unroll
    for (int jj = 0; jj < 4; jj++) {
        int coll = WN + jj * 8 + cc;
        float bv0 = bias[n0 + coll];
        float bv1 = bias[n0 + coll + 1];
        #pragma unroll
        for (int i = 0; i < 4; i++) {
            int r0 = m0 + WM + i * 16 + cr;
            *(float2*)(C + (size_t)r0 * ldc + n0 + coll) =
                make_float2(acc[i][jj][0] + bv0, acc[i][jj][1] + bv1);
            *(float2*)(C + (size_t)(r0 + 8) * ldc + n0 + coll) =
                make_float2(acc[i][jj][2] + bv0, acc[i][jj][3] + bv1);
        }
    }
}

// ---------------------------------------------------------------------------
// Attention v3: R4 structure (scalar broadcast LDS) + 4-way ILP dot chains,
// V & mem_v in registers. One block per (b,n); warp = head.
// ---------------------------------------------------------------------------
__global__ __launch_bounds__(256) void attn3_kernel(
    const float* __restrict__ memk,
    const float* __restrict__ memv,
    const float* __restrict__ alpha,
    const float* __restrict__ QKV,
    __half* __restrict__ Oh, __half* __restrict__ Ol)
{
    __shared__ float sQ[HH][TT][33];
    __shared__ float sK[HH][TT][33];
    __shared__ float sS[HH][TT][13];
    __shared__ float sL[HH][TT][9];

    const int bn   = blockIdx.x;
    const int h    = threadIdx.x >> 5;
    const int lane = threadIdx.x & 31;
    const size_t rb = (size_t)bn * TT * 768;
    const float scale = 0.1767766952966369f;

    float v[TT];
    #pragma unroll
    for (int t = 0; t < TT; t++) {
        sQ[h][t][lane] = QKV[rb + (size_t)t * 768 +       h * 32 + lane];
        sK[h][t][lane] = QKV[rb + (size_t)t * 768 + 256 + h * 32 + lane];
        v[t]           = QKV[rb + (size_t)t * 768 + 512 + h * 32 + lane];
    }
    float mv[MM];
    #pragma unroll
    for (int m = 0; m < MM; m++) mv[m] = memv[((h << 3) + m) * 32 + lane];
    __syncwarp();

    // causal time scores: 4-way split accumulators
    for (int p = lane; p < 144; p += 32) {
        int t = p / 12, s = p - t * 12;
        if (s <= t) {
            float a0 = 0.f, a1 = 0.f, a2 = 0.f, a3 = 0.f;
            const float* q = sQ[h][t];
            const float* k = sK[h][s];
            #pragma unroll
            for (int c = 0; c < 8; c++) {
                a0 = fmaf(q[c * 4 + 0], k[c * 4 + 0], a0);
                a1 = fmaf(q[c * 4 + 1], k[c * 4 + 1], a1);
                a2 = fmaf(q[c * 4 + 2], k[c * 4 + 2], a2);
                a3 = fmaf(q[c * 4 + 3], k[c * 4 + 3], a3);
            }
            sS[h][t][s] = ((a0 + a1) + (a2 + a3)) * scale;
        }
    }
    // memory-bank scores
    for (int p = lane; p < 96; p += 32) {
        int t = p >> 3, m = p & 7;
        const float* q  = sQ[h][t];
        const float* mk = memk + ((h << 3) + m) * 32;
        float a0 = 0.f, a1 = 0.f, a2 = 0.f, a3 = 0.f;
        #pragma unroll
        for (int c = 0; c < 8; c++) {
            a0 = fmaf(q[c * 4 + 0], mk[c * 4 + 0], a0);
            a1 = fmaf(q[c * 4 + 1], mk[c * 4 + 1], a1);
            a2 = fmaf(q[c * 4 + 2], mk[c * 4 + 2], a2);
            a3 = fmaf(q[c * 4 + 3], mk[c * 4 + 3], a3);
        }
        sL[h][t][m] = ((a0 + a1) + (a2 + a3)) * scale;
    }
    __syncwarp();

    // per-row softmax (lane t < 12)
    if (lane < TT) {
        int t = lane;
        float mx = -1e30f;
        for (int s = 0; s <= t; s++) mx = fmaxf(mx, sS[h][t][s]);
        float sum = 0.f;
        for (int s = 0; s <= t; s++) { float e = __expf(sS[h][t][s] - mx); sS[h][t][s] = e; sum += e; }
        float inv = 1.f / sum;
        for (int s = 0; s <= t; s++) sS[h][t][s] *= inv;

        mx = -1e30f;
        #pragma unroll
        for (int m = 0; m < MM; m++) mx = fmaxf(mx, sL[h][t][m]);
        sum = 0.f;
        #pragma unroll
        for (int m = 0; m < MM; m++) { float e = __expf(sL[h][t][m] - mx); sL[h][t][m] = e; sum += e; }
        inv = 1.f / sum;
        #pragma unroll
        for (int m = 0; m < MM; m++) sL[h][t][m] *= inv;
    }
    __syncwarp();

    const float wl = 1.f / (1.f + __expf(-alpha[0]));
    const float wt = 1.f - wl;

    // outputs: probs broadcast from smem (1 wavefront), V in regs
    #pragma unroll
    for (int t = 0; t < TT; t++) {
        float o0 = 0.f, o1 = 0.f;
        for (int s = 0; s + 1 <= t; s += 2) {
            o0 = fmaf(sS[h][t][s],     v[s],     o0);
            o1 = fmaf(sS[h][t][s + 1], v[s + 1], o1);
        }
        if ((t & 1) == 0) o0 = fmaf(sS[h][t][t], v[t], o0);
        float l0 = 0.f, l1 = 0.f;
        #pragma unroll
        for (int m = 0; m < MM; m += 2) {
            l0 = fmaf(sL[h][t][m],     mv[m],     l0);
            l1 = fmaf(sL[h][t][m + 1], mv[m + 1], l1);
        }
        float o = (o0 + o1) * wt + (l0 + l1) * wl;
        size_t oi = (size_t)bn * TT * 256 + (size_t)t * 256 + h * 32 + lane;
        __half hi = __float2half_rn(o);
        Oh[oi] = hi;
        Ol[oi] = __float2half_rn(o - __half2float(hi));
    }
}

// ---------------------------------------------------------------------------
// Residual + LayerNorm: one warp per row of 256.
// ---------------------------------------------------------------------------
__global__ __launch_bounds__(256) void ln_kernel(
    const float* __restrict__ Y, const float* __restrict__ X,
    const float* __restrict__ gamma, const float* __restrict__ beta,
    float* __restrict__ out)
{
    int gw   = (blockIdx.x * blockDim.x + threadIdx.x) >> 5;
    int lane = threadIdx.x & 31;
    if (gw >= ROWS) return;
    size_t base = (size_t)gw * 256 + lane * 8;

    float4 y1 = *(const float4*)(Y + base);
    float4 y2 = *(const float4*)(Y + base + 4);
    float4 x1 = *(const float4*)(X + base);
    float4 x2 = *(const float4*)(X + base + 4);
    float hh[8] = { y1.x + x1.x, y1.y + x1.y, y1.z + x1.z, y1.w + x1.w,
                    y2.x + x2.x, y2.y + x2.y, y2.z + x2.z, y2.w + x2.w };

    float s = 0.f, sq = 0.f;
    #pragma unroll
    for (int i = 0; i < 8; i++) { s += hh[i]; sq += hh[i] * hh[i]; }
    #pragma unroll
    for (int off = 16; off; off >>= 1) {
        s  += __shfl_xor_sync(0xFFFFFFFFu, s,  off);
        sq += __shfl_xor_sync(0xFFFFFFFFu, sq, off);
    }
    float mu  = s * (1.f / 256.f);
    float var = sq * (1.f / 256.f) - mu * mu;
    float rs  = rsqrtf(var + 1e-5f);

    float4 g1 = *(const float4*)(gamma + lane * 8);
    float4 g2 = *(const float4*)(gamma + lane * 8 + 4);
    float4 be1 = *(const float4*)(beta + lane * 8);
    float4 be2 = *(const float4*)(beta + lane * 8 + 4);

    float4 o1 = make_float4((hh[0] - mu) * rs * g1.x + be1.x,
                            (hh[1] - mu) * rs * g1.y + be1.y,
                            (hh[2] - mu) * rs * g1.z + be1.z,
                            (hh[3] - mu) * rs * g1.w + be1.w);
    float4 o2 = make_float4((hh[4] - mu) * rs * g2.x + be2.x,
                            (hh[5] - mu) * rs * g2.y + be2.y,
                            (hh[6] - mu) * rs * g2.z + be2.z,
                            (hh[7] - mu) * rs * g2.w + be2.w);
    *(float4*)(out + base)     = o1;
    *(float4*)(out + base + 4) = o2;
}

// ---------------------------------------------------------------------------
extern "C" void kernel_launch(void* const* d_in, const int* in_sizes, int n_in,
                              void* d_out, int out_size)
{
    const float* x     = (const float*)d_in[0];
    const float* Wq    = (const float*)d_in[1];
    const float* bq    = (const float*)d_in[2];
    const float* Wk    = (const float*)d_in[3];
    const float* bk    = (const float*)d_in[4];
    const float* Wv    = (const float*)d_in[5];
    const float* bv    = (const float*)d_in[6];
    const float* memk  = (const float*)d_in[7];
    const float* memv  = (const float*)d_in[8];
    const float* fcw   = (const float*)d_in[9];
    const float* fcb   = (const float*)d_in[10];
    const float* gamma = (const float*)d_in[11];
    const float* beta  = (const float*)d_in[12];
    const float* alpha = (const float*)d_in[13];
    float* out = (float*)d_out;

    float *qkv, *fc, *bias;
    __half *xh, *xl, *ah, *al, *wh, *wlp;
    cudaGetSymbolAddress((void**)&qkv, g_qkv);
    cudaGetSymbolAddress((void**)&fc,  g_fc);
    cudaGetSymbolAddress((void**)&xh,  g_xh);
    cudaGetSymbolAddress((void**)&xl,  g_xl);
    cudaGetSymbolAddress((void**)&ah,  g_ah);
    cudaGetSymbolAddress((void**)&al,  g_al);
    cudaGetSymbolAddress((void**)&wh,  g_wh);
    cudaGetSymbolAddress((void**)&wlp, g_wl);
    cudaGetSymbolAddress((void**)&bias, g_bias);

    const int smem = NSTAGE * 4 * STG * 2;  // 98304 bytes
    cudaFuncSetAttribute(gemm_f16s, cudaFuncAttributeMaxDynamicSharedMemorySize, smem);

    // 0) split-convert inputs
    cvt_split<<<(unsigned)(XELEMS / 4 / 256), 256>>>(x, xh, xl, XELEMS);
    cvt_weights<<<256, 256>>>(Wq, Wk, Wv, fcw, bq, bk, bv, fcb);

    // 1) fused QKV projection
    {
        dim3 grid(6, ROWS / 128);
        gemm_f16s<<<grid, 256, smem>>>(xh, xl, wh, wlp, bias, qkv, 768);
    }
    // 2) attention per (b,n) -> hi/lo split output
    attn3_kernel<<<BNTOT, 256>>>(memk, memv, alpha, qkv, ah, al);

    // 3) FC projection
    {
        dim3 grid(2, ROWS / 128);
        gemm_f16s<<<grid, 256, smem>>>(ah, al, wh + 768 * 256, wlp + 768 * 256,
                                       bias + 768, fc, 256);
    }
    // 4) residual + LayerNorm
    ln_kernel<<<(ROWS * 32 + 255) / 256, 256>>>(fc, x, gamma, beta, out);
}

// round 11
// speedup vs baseline: 1.1670x; 1.0146x over previous
#include <cuda_runtime.h>
#include <cuda_fp16.h>
#include <cstdint>

// Problem constants
#define BB 8
#define NN 2048
#define TT 12
#define DD 256
#define HH 8
#define DKK 32
#define MM 8

#define ROWS (BB*NN*TT)     // 196608
#define BNTOT (BB*NN)       // 16384
#define XELEMS ((size_t)ROWS * 256)

// Scratch (device globals: allocation-free kernel_launch)
__device__ float  g_qkv[(size_t)ROWS * 768];
__device__ float  g_fc [(size_t)ROWS * 256];
__device__ __half g_xh [XELEMS];
__device__ __half g_xl [XELEMS];
__device__ __half g_ah [XELEMS];
__device__ __half g_al [XELEMS];
__device__ __half g_wh [1024 * 256];
__device__ __half g_wl [1024 * 256];
__device__ float  g_bias[1024];

// Triangular job decode tables (78 causal (t,s) pairs)
__constant__ unsigned char cJobT[78] = {
    0, 1,1, 2,2,2, 3,3,3,3, 4,4,4,4,4, 5,5,5,5,5,5,
    6,6,6,6,6,6,6, 7,7,7,7,7,7,7,7, 8,8,8,8,8,8,8,8,8,
    9,9,9,9,9,9,9,9,9,9, 10,10,10,10,10,10,10,10,10,10,10,
    11,11,11,11,11,11,11,11,11,11,11,11 };
__constant__ unsigned char cJobS[78] = {
    0, 0,1, 0,1,2, 0,1,2,3, 0,1,2,3,4, 0,1,2,3,4,5,
    0,1,2,3,4,5,6, 0,1,2,3,4,5,6,7, 0,1,2,3,4,5,6,7,8,
    0,1,2,3,4,5,6,7,8,9, 0,1,2,3,4,5,6,7,8,9,10,
    0,1,2,3,4,5,6,7,8,9,10,11 };

// ---------------------------------------------------------------------------
// Split-conversion helpers
// ---------------------------------------------------------------------------
__device__ __forceinline__ uint32_t pack2(__half a, __half b) {
    __half2 h = __halves2half2(a, b);
    return *(uint32_t*)&h;
}

__global__ __launch_bounds__(256) void cvt_split(
    const float* __restrict__ in, __half* __restrict__ hi, __half* __restrict__ lo, size_t n)
{
    size_t i = ((size_t)blockIdx.x * blockDim.x + threadIdx.x) * 4;
    if (i >= n) return;
    float4 v = *(const float4*)(in + i);
    __half h0 = __float2half_rn(v.x), h1 = __float2half_rn(v.y);
    __half h2 = __float2half_rn(v.z), h3 = __float2half_rn(v.w);
    *(uint2*)(hi + i) = make_uint2(pack2(h0, h1), pack2(h2, h3));
    *(uint2*)(lo + i) = make_uint2(
        pack2(__float2half_rn(v.x - __half2float(h0)), __float2half_rn(v.y - __half2float(h1))),
        pack2(__float2half_rn(v.z - __half2float(h2)), __float2half_rn(v.w - __half2float(h3))));
}

__global__ __launch_bounds__(256) void cvt_weights(
    const float* __restrict__ Wq, const float* __restrict__ Wk,
    const float* __restrict__ Wv, const float* __restrict__ Wf,
    const float* __restrict__ bq, const float* __restrict__ bk,
    const float* __restrict__ bv, const float* __restrict__ bf)
{
    size_t i = ((size_t)blockIdx.x * blockDim.x + threadIdx.x) * 4;
    if (i < 4 * 65536) {
        int mat = (int)(i >> 16);
        size_t off = i & 65535;
        const float* W = (mat == 0) ? Wq : (mat == 1 ? Wk : (mat == 2 ? Wv : Wf));
        float4 v = *(const float4*)(W + off);
        __half h0 = __float2half_rn(v.x), h1 = __float2half_rn(v.y);
        __half h2 = __float2half_rn(v.z), h3 = __float2half_rn(v.w);
        *(uint2*)(g_wh + i) = make_uint2(pack2(h0, h1), pack2(h2, h3));
        *(uint2*)(g_wl + i) = make_uint2(
            pack2(__float2half_rn(v.x - __half2float(h0)), __float2half_rn(v.y - __half2float(h1))),
            pack2(__float2half_rn(v.z - __half2float(h2)), __float2half_rn(v.w - __half2float(h3))));
    }
    int t = blockIdx.x * blockDim.x + threadIdx.x;
    if (t < 256)        g_bias[t] = bq[t];
    else if (t < 512)   g_bias[t] = bk[t - 256];
    else if (t < 768)   g_bias[t] = bv[t - 512];
    else if (t < 1024)  g_bias[t] = bf[t - 768];
}

// ---------------------------------------------------------------------------
// Tensor-core GEMM (unchanged from R6): pre-split fp16 planes, 3-term split.
// Block 128x128, 256 threads, 8 warps, warp tile 64x32, BK=16,
// 4-stage cp.async ring, one __syncthreads per stage.
// ---------------------------------------------------------------------------
#define ASTR 24
#define STG  (128 * ASTR)
#define NSTAGE 4

__device__ __forceinline__ void ldsm4(uint32_t* r, const __half* p) {
    uint32_t a = (uint32_t)__cvta_generic_to_shared(p);
    asm volatile("ldmatrix.sync.aligned.m8n8.x4.shared.b16 {%0,%1,%2,%3}, [%4];"
                 : "=r"(r[0]), "=r"(r[1]), "=r"(r[2]), "=r"(r[3]) : "r"(a));
}
__device__ __forceinline__ void mma16816(float* d, const uint32_t* a, const uint32_t* b) {
    asm volatile("mma.sync.aligned.m16n8k16.row.col.f32.f16.f16.f32 "
        "{%0,%1,%2,%3}, {%4,%5,%6,%7}, {%8,%9}, {%0,%1,%2,%3};"
        : "+f"(d[0]), "+f"(d[1]), "+f"(d[2]), "+f"(d[3])
        : "r"(a[0]), "r"(a[1]), "r"(a[2]), "r"(a[3]), "r"(b[0]), "r"(b[1]));
}
__device__ __forceinline__ void cpa16(__half* dst, const __half* src) {
    uint32_t d = (uint32_t)__cvta_generic_to_shared(dst);
    asm volatile("cp.async.cg.shared.global [%0], [%1], 16;" :: "r"(d), "l"(src));
}

__global__ __launch_bounds__(256, 2) void gemm_f16s(
    const __half* __restrict__ Ah, const __half* __restrict__ Al,
    const __half* __restrict__ Wh, const __half* __restrict__ Wl,
    const float* __restrict__ bias,
    float* __restrict__ C, int ldc)
{
    extern __shared__ __half sm[];

    const int tid  = threadIdx.x;
    const int m0   = blockIdx.y * 128;
    const int n0   = blockIdx.x * 128;
    const int wid  = tid >> 5;
    const int lane = tid & 31;
    const int WM = (wid & 1) * 64;
    const int WN = (wid >> 1) * 32;

    const int lrow = tid >> 1;
    const int lch  = (tid & 1) * 8;
    const size_t aoff = (size_t)(m0 + lrow) * 256 + lch;
    const size_t boff = (size_t)(n0 + lrow) * 256 + lch;
    const int sdst = lrow * ASTR + lch;

    float acc[4][4][4];
    #pragma unroll
    for (int i = 0; i < 4; i++)
        #pragma unroll
        for (int j = 0; j < 4; j++)
            #pragma unroll
            for (int e = 0; e < 4; e++) acc[i][j][e] = 0.f;

    auto load_stage = [&](int k0, int buf) {
        __half* b = sm + buf * 4 * STG;
        cpa16(b + 0 * STG + sdst, Ah + aoff + k0);
        cpa16(b + 1 * STG + sdst, Al + aoff + k0);
        cpa16(b + 2 * STG + sdst, Wh + boff + k0);
        cpa16(b + 3 * STG + sdst, Wl + boff + k0);
        asm volatile("cp.async.commit_group;");
    };

    load_stage(0, 0);
    load_stage(16, 1);
    load_stage(32, 2);

    for (int s = 0; s < 16; s++) {
        if (s <= 13)      asm volatile("cp.async.wait_group 2;");
        else if (s == 14) asm volatile("cp.async.wait_group 1;");
        else              asm volatile("cp.async.wait_group 0;");
        __syncthreads();

        if (s <= 12) load_stage((s + 3) * 16, (s + 3) & 3);

        const __half* bAh = sm + (s & 3) * 4 * STG;
        const __half* bAl = bAh + STG;
        const __half* bBh = bAh + 2 * STG;
        const __half* bBl = bAh + 3 * STG;

        uint32_t ah[4][4], al[4][4], bh[2][4], bl[2][4];
        const int ar = WM + (lane & 15);
        const int ac = (lane & 16) >> 1;
        #pragma unroll
        for (int i = 0; i < 4; i++) {
            ldsm4(ah[i], bAh + (ar + i * 16) * ASTR + ac);
            ldsm4(al[i], bAl + (ar + i * 16) * ASTR + ac);
        }
        const int br = WN + (lane & 7) + ((lane & 16) >> 1);
        const int bc = lane & 8;
        #pragma unroll
        for (int j = 0; j < 2; j++) {
            ldsm4(bh[j], bBh + (br + j * 16) * ASTR + bc);
            ldsm4(bl[j], bBl + (br + j * 16) * ASTR + bc);
        }
        #pragma unroll
        for (int i = 0; i < 4; i++) {
            #pragma unroll
            for (int jj = 0; jj < 4; jj++) {
                const uint32_t* bhp = &bh[jj >> 1][(jj & 1) * 2];
                const uint32_t* blp = &bl[jj >> 1][(jj & 1) * 2];
                mma16816(acc[i][jj], ah[i], bhp);
                mma16816(acc[i][jj], al[i], bhp);
                mma16816(acc[i][jj], ah[i], blp);
            }
        }
    }

    const int cr = lane >> 2;
    const int cc = (lane & 3) * 2;
    #pragma unroll
    for (int jj = 0; jj < 4; jj++) {
        int coll = WN + jj * 8 + cc;
        float bv0 = bias[n0 + coll];
        float bv1 = bias[n0 + coll + 1];
        #pragma unroll
        for (int i = 0; i < 4; i++) {
            int r0 = m0 + WM + i * 16 + cr;
            *(float2*)(C + (size_t)r0 * ldc + n0 + coll) =
                make_float2(acc[i][jj][0] + bv0, acc[i][jj][1] + bv1);
            *(float2*)(C + (size_t)(r0 + 8) * ldc + n0 + coll) =
                make_float2(acc[i][jj][2] + bv0, acc[i][jj][3] + bv1);
        }
    }
}

// ---------------------------------------------------------------------------
// Attention v4: group-of-4 cooperative dots (LDS.128 + shfl butterfly).
// One block per (b,n); warp = head. V & mem_v in registers.
// ---------------------------------------------------------------------------
__global__ __launch_bounds__(256) void attn4_kernel(
    const float* __restrict__ memk,
    const float* __restrict__ memv,
    const float* __restrict__ alpha,
    const float* __restrict__ QKV,
    __half* __restrict__ Oh, __half* __restrict__ Ol)
{
    __shared__ float sQ [HH][TT][36];
    __shared__ float sK [HH][TT][36];
    __shared__ float sMK[HH][MM][36];
    __shared__ float sS [HH][TT][13];
    __shared__ float sL [HH][TT][9];

    const int bn   = blockIdx.x;
    const int h    = threadIdx.x >> 5;
    const int lane = threadIdx.x & 31;
    const int grp  = lane >> 2;      // 0..7
    const int sub  = lane & 3;       // 0..3
    const size_t rb = (size_t)bn * TT * 768;
    const float scale = 0.1767766952966369f;

    float v[TT];
    #pragma unroll
    for (int t = 0; t < TT; t++) {
        sQ[h][t][lane] = QKV[rb + (size_t)t * 768 +       h * 32 + lane];
        sK[h][t][lane] = QKV[rb + (size_t)t * 768 + 256 + h * 32 + lane];
        v[t]           = QKV[rb + (size_t)t * 768 + 512 + h * 32 + lane];
    }
    // memk -> smem: lane covers row (lane>>2), cols (lane&3)*8 .. +7
    {
        int mr = lane >> 2, mc = (lane & 3) * 8;
        const float* src = memk + ((h << 3) + mr) * 32 + mc;
        #pragma unroll
        for (int e = 0; e < 8; e++) sMK[h][mr][mc + e] = src[e];
    }
    float mv[MM];
    #pragma unroll
    for (int m = 0; m < MM; m++) mv[m] = memv[((h << 3) + m) * 32 + lane];
    __syncwarp();

    // 174 score jobs (78 causal + 96 memory), 4 lanes per job, 22 uniform sweeps
    #pragma unroll 1
    for (int it = 0; it < 22; it++) {
        int j = it * 8 + grp;
        int jc = (j < 174) ? j : 173;
        const float4 *q4, *k4;
        int t, s;                    // s: causal col or memory slot
        bool causal;
        if (jc < 78) {
            t = cJobT[jc]; s = cJobS[jc];
            causal = true;
            q4 = (const float4*)sQ[h][t];
            k4 = (const float4*)sK[h][s];
        } else {
            int jm = jc - 78;
            t = jm >> 3; s = jm & 7;
            causal = false;
            q4 = (const float4*)sQ[h][t];
            k4 = (const float4*)sMK[h][s];
        }
        float4 qa = q4[sub * 2], qb = q4[sub * 2 + 1];
        float4 ka = k4[sub * 2], kb = k4[sub * 2 + 1];
        float p0 = qa.x * ka.x + qa.y * ka.y + qa.z * ka.z + qa.w * ka.w;
        float p1 = qb.x * kb.x + qb.y * kb.y + qb.z * kb.z + qb.w * kb.w;
        float p = p0 + p1;
        p += __shfl_xor_sync(0xFFFFFFFFu, p, 1);
        p += __shfl_xor_sync(0xFFFFFFFFu, p, 2);
        if (sub == 0 && j < 174) {
            if (causal) sS[h][t][s] = p * scale;
            else        sL[h][t][s] = p * scale;
        }
    }
    __syncwarp();

    // per-row softmax (lane t < 12)
    if (lane < TT) {
        int t = lane;
        float mx = -1e30f;
        for (int s = 0; s <= t; s++) mx = fmaxf(mx, sS[h][t][s]);
        float sum = 0.f;
        for (int s = 0; s <= t; s++) { float e = __expf(sS[h][t][s] - mx); sS[h][t][s] = e; sum += e; }
        float inv = 1.f / sum;
        for (int s = 0; s <= t; s++) sS[h][t][s] *= inv;

        mx = -1e30f;
        #pragma unroll
        for (int m = 0; m < MM; m++) mx = fmaxf(mx, sL[h][t][m]);
        sum = 0.f;
        #pragma unroll
        for (int m = 0; m < MM; m++) { float e = __expf(sL[h][t][m] - mx); sL[h][t][m] = e; sum += e; }
        inv = 1.f / sum;
        #pragma unroll
        for (int m = 0; m < MM; m++) sL[h][t][m] *= inv;
    }
    __syncwarp();

    const float wl = 1.f / (1.f + __expf(-alpha[0]));
    const float wt = 1.f - wl;

    #pragma unroll
    for (int t = 0; t < TT; t++) {
        float o0 = 0.f, o1 = 0.f;
        for (int s = 0; s + 1 <= t; s += 2) {
            o0 = fmaf(sS[h][t][s],     v[s],     o0);
            o1 = fmaf(sS[h][t][s + 1], v[s + 1], o1);
        }
        if ((t & 1) == 0) o0 = fmaf(sS[h][t][t], v[t], o0);
        float l0 = 0.f, l1 = 0.f;
        #pragma unroll
        for (int m = 0; m < MM; m += 2) {
            l0 = fmaf(sL[h][t][m],     mv[m],     l0);
            l1 = fmaf(sL[h][t][m + 1], mv[m + 1], l1);
        }
        float o = (o0 + o1) * wt + (l0 + l1) * wl;
        size_t oi = (size_t)bn * TT * 256 + (size_t)t * 256 + h * 32 + lane;
        __half hi = __float2half_rn(o);
        Oh[oi] = hi;
        Ol[oi] = __float2half_rn(o - __half2float(hi));
    }
}

// ---------------------------------------------------------------------------
// Residual + LayerNorm: one warp per row of 256.
// ---------------------------------------------------------------------------
__global__ __launch_bounds__(256) void ln_kernel(
    const float* __restrict__ Y, const float* __restrict__ X,
    const float* __restrict__ gamma, const float* __restrict__ beta,
    float* __restrict__ out)
{
    int gw   = (blockIdx.x * blockDim.x + threadIdx.x) >> 5;
    int lane = threadIdx.x & 31;
    if (gw >= ROWS) return;
    size_t base = (size_t)gw * 256 + lane * 8;

    float4 y1 = *(const float4*)(Y + base);
    float4 y2 = *(const float4*)(Y + base + 4);
    float4 x1 = *(const float4*)(X + base);
    float4 x2 = *(const float4*)(X + base + 4);
    float hh[8] = { y1.x + x1.x, y1.y + x1.y, y1.z + x1.z, y1.w + x1.w,
                    y2.x + x2.x, y2.y + x2.y, y2.z + x2.z, y2.w + x2.w };

    float s = 0.f, sq = 0.f;
    #pragma unroll
    for (int i = 0; i < 8; i++) { s += hh[i]; sq += hh[i] * hh[i]; }
    #pragma unroll
    for (int off = 16; off; off >>= 1) {
        s  += __shfl_xor_sync(0xFFFFFFFFu, s,  off);
        sq += __shfl_xor_sync(0xFFFFFFFFu, sq, off);
    }
    float mu  = s * (1.f / 256.f);
    float var = sq * (1.f / 256.f) - mu * mu;
    float rs  = rsqrtf(var + 1e-5f);

    float4 g1 = *(const float4*)(gamma + lane * 8);
    float4 g2 = *(const float4*)(gamma + lane * 8 + 4);
    float4 be1 = *(const float4*)(beta + lane * 8);
    float4 be2 = *(const float4*)(beta + lane * 8 + 4);

    float4 o1 = make_float4((hh[0] - mu) * rs * g1.x + be1.x,
                            (hh[1] - mu) * rs * g1.y + be1.y,
                            (hh[2] - mu) * rs * g1.z + be1.z,
                            (hh[3] - mu) * rs * g1.w + be1.w);
    float4 o2 = make_float4((hh[4] - mu) * rs * g2.x + be2.x,
                            (hh[5] - mu) * rs * g2.y + be2.y,
                            (hh[6] - mu) * rs * g2.z + be2.z,
                            (hh[7] - mu) * rs * g2.w + be2.w);
    *(float4*)(out + base)     = o1;
    *(float4*)(out + base + 4) = o2;
}

// ---------------------------------------------------------------------------
extern "C" void kernel_launch(void* const* d_in, const int* in_sizes, int n_in,
                              void* d_out, int out_size)
{
    const float* x     = (const float*)d_in[0];
    const float* Wq    = (const float*)d_in[1];
    const float* bq    = (const float*)d_in[2];
    const float* Wk    = (const float*)d_in[3];
    const float* bk    = (const float*)d_in[4];
    const float* Wv    = (const float*)d_in[5];
    const float* bv    = (const float*)d_in[6];
    const float* memk  = (const float*)d_in[7];
    const float* memv  = (const float*)d_in[8];
    const float* fcw   = (const float*)d_in[9];
    const float* fcb   = (const float*)d_in[10];
    const float* gamma = (const float*)d_in[11];
    const float* beta  = (const float*)d_in[12];
    const float* alpha = (const float*)d_in[13];
    float* out = (float*)d_out;

    float *qkv, *fc, *bias;
    __half *xh, *xl, *ah, *al, *wh, *wlp;
    cudaGetSymbolAddress((void**)&qkv, g_qkv);
    cudaGetSymbolAddress((void**)&fc,  g_fc);
    cudaGetSymbolAddress((void**)&xh,  g_xh);
    cudaGetSymbolAddress((void**)&xl,  g_xl);
    cudaGetSymbolAddress((void**)&ah,  g_ah);
    cudaGetSymbolAddress((void**)&al,  g_al);
    cudaGetSymbolAddress((void**)&wh,  g_wh);
    cudaGetSymbolAddress((void**)&wlp, g_wl);
    cudaGetSymbolAddress((void**)&bias, g_bias);

    const int smem = NSTAGE * 4 * STG * 2;  // 98304 bytes
    cudaFuncSetAttribute(gemm_f16s, cudaFuncAttributeMaxDynamicSharedMemorySize, smem);

    // 0) split-convert inputs
    cvt_split<<<(unsigned)(XELEMS / 4 / 256), 256>>>(x, xh, xl, XELEMS);
    cvt_weights<<<256, 256>>>(Wq, Wk, Wv, fcw, bq, bk, bv, fcb);

    // 1) fused QKV projection
    {
        dim3 grid(6, ROWS / 128);
        gemm_f16s<<<grid, 256, smem>>>(xh, xl, wh, wlp, bias, qkv, 768);
    }
    // 2) attention per (b,n) -> hi/lo split output
    attn4_kernel<<<BNTOT, 256>>>(memk, memv, alpha, qkv, ah, al);

    // 3) FC projection
    {
        dim3 grid(2, ROWS / 128);
        gemm_f16s<<<grid, 256, smem>>>(ah, al, wh + 768 * 256, wlp + 768 * 256,
                                       bias + 768, fc, 256);
    }
    // 4) residual + LayerNorm
    ln_kernel<<<(ROWS * 32 + 255) / 256, 256>>>(fc, x, gamma, beta, out);
}

// round 12
// speedup vs baseline: 1.4820x; 1.2700x over previous
#include <cuda_runtime.h>
#include <cuda_fp16.h>
#include <cstdint>

// Problem constants
#define BB 8
#define NN 2048
#define TT 12
#define DD 256
#define HH 8
#define DKK 32
#define MM 8

#define ROWS (BB*NN*TT)     // 196608
#define BNTOT (BB*NN)       // 16384
#define XELEMS ((size_t)ROWS * 256)

// Scratch (device globals: allocation-free kernel_launch)
__device__ float  g_qkv[(size_t)ROWS * 768];
__device__ float  g_fc [(size_t)ROWS * 256];
__device__ __half g_xh [XELEMS];
__device__ __half g_xl [XELEMS];
__device__ __half g_ah [XELEMS];
__device__ __half g_al [XELEMS];
__device__ __half g_wh [1024 * 256];
__device__ float  g_bias[1024];

// Triangular job decode tables (78 causal (t,s) pairs)
__constant__ unsigned char cJobT[78] = {
    0, 1,1, 2,2,2, 3,3,3,3, 4,4,4,4,4, 5,5,5,5,5,5,
    6,6,6,6,6,6,6, 7,7,7,7,7,7,7,7, 8,8,8,8,8,8,8,8,8,
    9,9,9,9,9,9,9,9,9,9, 10,10,10,10,10,10,10,10,10,10,10,
    11,11,11,11,11,11,11,11,11,11,11,11 };
__constant__ unsigned char cJobS[78] = {
    0, 0,1, 0,1,2, 0,1,2,3, 0,1,2,3,4, 0,1,2,3,4,5,
    0,1,2,3,4,5,6, 0,1,2,3,4,5,6,7, 0,1,2,3,4,5,6,7,8,
    0,1,2,3,4,5,6,7,8,9, 0,1,2,3,4,5,6,7,8,9,10,
    0,1,2,3,4,5,6,7,8,9,10,11 };

// ---------------------------------------------------------------------------
// Split-conversion helpers
// ---------------------------------------------------------------------------
__device__ __forceinline__ uint32_t pack2(__half a, __half b) {
    __half2 h = __halves2half2(a, b);
    return *(uint32_t*)&h;
}

__global__ __launch_bounds__(256) void cvt_split(
    const float* __restrict__ in, __half* __restrict__ hi, __half* __restrict__ lo, size_t n)
{
    size_t i = ((size_t)blockIdx.x * blockDim.x + threadIdx.x) * 4;
    if (i >= n) return;
    float4 v = *(const float4*)(in + i);
    __half h0 = __float2half_rn(v.x), h1 = __float2half_rn(v.y);
    __half h2 = __float2half_rn(v.z), h3 = __float2half_rn(v.w);
    *(uint2*)(hi + i) = make_uint2(pack2(h0, h1), pack2(h2, h3));
    *(uint2*)(lo + i) = make_uint2(
        pack2(__float2half_rn(v.x - __half2float(h0)), __float2half_rn(v.y - __half2float(h1))),
        pack2(__float2half_rn(v.z - __half2float(h2)), __float2half_rn(v.w - __half2float(h3))));
}

// weights: 4 matrices of 256x256 -> concatenated 1024x256 hi plane; bias concat
__global__ __launch_bounds__(256) void cvt_weights(
    const float* __restrict__ Wq, const float* __restrict__ Wk,
    const float* __restrict__ Wv, const float* __restrict__ Wf,
    const float* __restrict__ bq, const float* __restrict__ bk,
    const float* __restrict__ bv, const float* __restrict__ bf)
{
    size_t i = ((size_t)blockIdx.x * blockDim.x + threadIdx.x) * 4;
    if (i < 4 * 65536) {
        int mat = (int)(i >> 16);
        size_t off = i & 65535;
        const float* W = (mat == 0) ? Wq : (mat == 1 ? Wk : (mat == 2 ? Wv : Wf));
        float4 v = *(const float4*)(W + off);
        *(uint2*)(g_wh + i) = make_uint2(
            pack2(__float2half_rn(v.x), __float2half_rn(v.y)),
            pack2(__float2half_rn(v.z), __float2half_rn(v.w)));
    }
    int t = blockIdx.x * blockDim.x + threadIdx.x;
    if (t < 256)        g_bias[t] = bq[t];
    else if (t < 512)   g_bias[t] = bk[t - 256];
    else if (t < 768)   g_bias[t] = bv[t - 512];
    else if (t < 1024)  g_bias[t] = bf[t - 768];
}

// ---------------------------------------------------------------------------
// Tensor-core GEMM, 2-term split: D = (Ahi + Alo) * Bf16.
// Block 128x128, 256 threads, 8 warps, warp tile 64x32, BK=16,
// 4-stage cp.async ring (3 planes/stage), one __syncthreads per stage.
// ---------------------------------------------------------------------------
#define ASTR 24
#define STG  (128 * ASTR)
#define NSTAGE 4

__device__ __forceinline__ void ldsm4(uint32_t* r, const __half* p) {
    uint32_t a = (uint32_t)__cvta_generic_to_shared(p);
    asm volatile("ldmatrix.sync.aligned.m8n8.x4.shared.b16 {%0,%1,%2,%3}, [%4];"
                 : "=r"(r[0]), "=r"(r[1]), "=r"(r[2]), "=r"(r[3]) : "r"(a));
}
__device__ __forceinline__ void mma16816(float* d, const uint32_t* a, const uint32_t* b) {
    asm volatile("mma.sync.aligned.m16n8k16.row.col.f32.f16.f16.f32 "
        "{%0,%1,%2,%3}, {%4,%5,%6,%7}, {%8,%9}, {%0,%1,%2,%3};"
        : "+f"(d[0]), "+f"(d[1]), "+f"(d[2]), "+f"(d[3])
        : "r"(a[0]), "r"(a[1]), "r"(a[2]), "r"(a[3]), "r"(b[0]), "r"(b[1]));
}
__device__ __forceinline__ void cpa16(__half* dst, const __half* src) {
    uint32_t d = (uint32_t)__cvta_generic_to_shared(dst);
    asm volatile("cp.async.cg.shared.global [%0], [%1], 16;" :: "r"(d), "l"(src));
}

__global__ __launch_bounds__(256, 2) void gemm_f16s(
    const __half* __restrict__ Ah, const __half* __restrict__ Al,
    const __half* __restrict__ Wh,
    const float* __restrict__ bias,
    float* __restrict__ C, int ldc)
{
    extern __shared__ __half sm[];   // [NSTAGE][3 planes][STG] = 72 KB

    const int tid  = threadIdx.x;
    const int m0   = blockIdx.y * 128;
    const int n0   = blockIdx.x * 128;
    const int wid  = tid >> 5;
    const int lane = tid & 31;
    const int WM = (wid & 1) * 64;
    const int WN = (wid >> 1) * 32;

    const int lrow = tid >> 1;
    const int lch  = (tid & 1) * 8;
    const size_t aoff = (size_t)(m0 + lrow) * 256 + lch;
    const size_t boff = (size_t)(n0 + lrow) * 256 + lch;
    const int sdst = lrow * ASTR + lch;

    float acc[4][4][4];
    #pragma unroll
    for (int i = 0; i < 4; i++)
        #pragma unroll
        for (int j = 0; j < 4; j++)
            #pragma unroll
            for (int e = 0; e < 4; e++) acc[i][j][e] = 0.f;

    auto load_stage = [&](int k0, int buf) {
        __half* b = sm + buf * 3 * STG;
        cpa16(b + 0 * STG + sdst, Ah + aoff + k0);
        cpa16(b + 1 * STG + sdst, Al + aoff + k0);
        cpa16(b + 2 * STG + sdst, Wh + boff + k0);
        asm volatile("cp.async.commit_group;");
    };

    load_stage(0, 0);
    load_stage(16, 1);
    load_stage(32, 2);

    for (int s = 0; s < 16; s++) {
        if (s <= 13)      asm volatile("cp.async.wait_group 2;");
        else if (s == 14) asm volatile("cp.async.wait_group 1;");
        else              asm volatile("cp.async.wait_group 0;");
        __syncthreads();

        if (s <= 12) load_stage((s + 3) * 16, (s + 3) & 3);

        const __half* bAh = sm + (s & 3) * 3 * STG;
        const __half* bAl = bAh + STG;
        const __half* bBh = bAh + 2 * STG;

        uint32_t ah[4][4], al[4][4], bh[2][4];
        const int ar = WM + (lane & 15);
        const int ac = (lane & 16) >> 1;
        #pragma unroll
        for (int i = 0; i < 4; i++) {
            ldsm4(ah[i], bAh + (ar + i * 16) * ASTR + ac);
            ldsm4(al[i], bAl + (ar + i * 16) * ASTR + ac);
        }
        const int br = WN + (lane & 7) + ((lane & 16) >> 1);
        const int bc = lane & 8;
        #pragma unroll
        for (int j = 0; j < 2; j++) {
            ldsm4(bh[j], bBh + (br + j * 16) * ASTR + bc);
        }
        #pragma unroll
        for (int i = 0; i < 4; i++) {
            #pragma unroll
            for (int jj = 0; jj < 4; jj++) {
                const uint32_t* bhp = &bh[jj >> 1][(jj & 1) * 2];
                mma16816(acc[i][jj], ah[i], bhp);
                mma16816(acc[i][jj], al[i], bhp);
            }
        }
    }

    const int cr = lane >> 2;
    const int cc = (lane & 3) * 2;
    #pragma unroll
    for (int jj = 0; jj < 4; jj++) {
        int coll = WN + jj * 8 + cc;
        float bv0 = bias[n0 + coll];
        float bv1 = bias[n0 + coll + 1];
        #pragma unroll
        for (int i = 0; i < 4; i++) {
            int r0 = m0 + WM + i * 16 + cr;
            *(float2*)(C + (size_t)r0 * ldc + n0 + coll) =
                make_float2(acc[i][jj][0] + bv0, acc[i][jj][1] + bv1);
            *(float2*)(C + (size_t)(r0 + 8) * ldc + n0 + coll) =
                make_float2(acc[i][jj][2] + bv0, acc[i][jj][3] + bv1);
        }
    }
}

// ---------------------------------------------------------------------------
// Attention v4 (unchanged from R11): group-of-4 cooperative dots.
// ---------------------------------------------------------------------------
__global__ __launch_bounds__(256) void attn4_kernel(
    const float* __restrict__ memk,
    const float* __restrict__ memv,
    const float* __restrict__ alpha,
    const float* __restrict__ QKV,
    __half* __restrict__ Oh, __half* __restrict__ Ol)
{
    __shared__ float sQ [HH][TT][36];
    __shared__ float sK [HH][TT][36];
    __shared__ float sMK[HH][MM][36];
    __shared__ float sS [HH][TT][13];
    __shared__ float sL [HH][TT][9];

    const int bn   = blockIdx.x;
    const int h    = threadIdx.x >> 5;
    const int lane = threadIdx.x & 31;
    const int grp  = lane >> 2;
    const int sub  = lane & 3;
    const size_t rb = (size_t)bn * TT * 768;
    const float scale = 0.1767766952966369f;

    float v[TT];
    #pragma unroll
    for (int t = 0; t < TT; t++) {
        sQ[h][t][lane] = QKV[rb + (size_t)t * 768 +       h * 32 + lane];
        sK[h][t][lane] = QKV[rb + (size_t)t * 768 + 256 + h * 32 + lane];
        v[t]           = QKV[rb + (size_t)t * 768 + 512 + h * 32 + lane];
    }
    {
        int mr = lane >> 2, mc = (lane & 3) * 8;
        const float* src = memk + ((h << 3) + mr) * 32 + mc;
        #pragma unroll
        for (int e = 0; e < 8; e++) sMK[h][mr][mc + e] = src[e];
    }
    float mv[MM];
    #pragma unroll
    for (int m = 0; m < MM; m++) mv[m] = memv[((h << 3) + m) * 32 + lane];
    __syncwarp();

    #pragma unroll 1
    for (int it = 0; it < 22; it++) {
        int j = it * 8 + grp;
        int jc = (j < 174) ? j : 173;
        const float4 *q4, *k4;
        int t, s;
        bool causal;
        if (jc < 78) {
            t = cJobT[jc]; s = cJobS[jc];
            causal = true;
            q4 = (const float4*)sQ[h][t];
            k4 = (const float4*)sK[h][s];
        } else {
            int jm = jc - 78;
            t = jm >> 3; s = jm & 7;
            causal = false;
            q4 = (const float4*)sQ[h][t];
            k4 = (const float4*)sMK[h][s];
        }
        float4 qa = q4[sub * 2], qb = q4[sub * 2 + 1];
        float4 ka = k4[sub * 2], kb = k4[sub * 2 + 1];
        float p0 = qa.x * ka.x + qa.y * ka.y + qa.z * ka.z + qa.w * ka.w;
        float p1 = qb.x * kb.x + qb.y * kb.y + qb.z * kb.z + qb.w * kb.w;
        float p = p0 + p1;
        p += __shfl_xor_sync(0xFFFFFFFFu, p, 1);
        p += __shfl_xor_sync(0xFFFFFFFFu, p, 2);
        if (sub == 0 && j < 174) {
            if (causal) sS[h][t][s] = p * scale;
            else        sL[h][t][s] = p * scale;
        }
    }
    __syncwarp();

    if (lane < TT) {
        int t = lane;
        float mx = -1e30f;
        for (int s = 0; s <= t; s++) mx = fmaxf(mx, sS[h][t][s]);
        float sum = 0.f;
        for (int s = 0; s <= t; s++) { float e = __expf(sS[h][t][s] - mx); sS[h][t][s] = e; sum += e; }
        float inv = 1.f / sum;
        for (int s = 0; s <= t; s++) sS[h][t][s] *= inv;

        mx = -1e30f;
        #pragma unroll
        for (int m = 0; m < MM; m++) mx = fmaxf(mx, sL[h][t][m]);
        sum = 0.f;
        #pragma unroll
        for (int m = 0; m < MM; m++) { float e = __expf(sL[h][t][m] - mx); sL[h][t][m] = e; sum += e; }
        inv = 1.f / sum;
        #pragma unroll
        for (int m = 0; m < MM; m++) sL[h][t][m] *= inv;
    }
    __syncwarp();

    const float wl = 1.f / (1.f + __expf(-alpha[0]));
    const float wt = 1.f - wl;

    #pragma unroll
    for (int t = 0; t < TT; t++) {
        float o0 = 0.f, o1 = 0.f;
        for (int s = 0; s + 1 <= t; s += 2) {
            o0 = fmaf(sS[h][t][s],     v[s],     o0);
            o1 = fmaf(sS[h][t][s + 1], v[s + 1], o1);
        }
        if ((t & 1) == 0) o0 = fmaf(sS[h][t][t], v[t], o0);
        float l0 = 0.f, l1 = 0.f;
        #pragma unroll
        for (int m = 0; m < MM; m += 2) {
            l0 = fmaf(sL[h][t][m],     mv[m],     l0);
            l1 = fmaf(sL[h][t][m + 1], mv[m + 1], l1);
        }
        float o = (o0 + o1) * wt + (l0 + l1) * wl;
        size_t oi = (size_t)bn * TT * 256 + (size_t)t * 256 + h * 32 + lane;
        __half hi = __float2half_rn(o);
        Oh[oi] = hi;
        Ol[oi] = __float2half_rn(o - __half2float(hi));
    }
}

// ---------------------------------------------------------------------------
// Residual + LayerNorm: one warp per row of 256.
// ---------------------------------------------------------------------------
__global__ __launch_bounds__(256) void ln_kernel(
    const float* __restrict__ Y, const float* __restrict__ X,
    const float* __restrict__ gamma, const float* __restrict__ beta,
    float* __restrict__ out)
{
    int gw   = (blockIdx.x * blockDim.x + threadIdx.x) >> 5;
    int lane = threadIdx.x & 31;
    if (gw >= ROWS) return;
    size_t base = (size_t)gw * 256 + lane * 8;

    float4 y1 = *(const float4*)(Y + base);
    float4 y2 = *(const float4*)(Y + base + 4);
    float4 x1 = *(const float4*)(X + base);
    float4 x2 = *(const float4*)(X + base + 4);
    float hh[8] = { y1.x + x1.x, y1.y + x1.y, y1.z + x1.z, y1.w + x1.w,
                    y2.x + x2.x, y2.y + x2.y, y2.z + x2.z, y2.w + x2.w };

    float s = 0.f, sq = 0.f;
    #pragma unroll
    for (int i = 0; i < 8; i++) { s += hh[i]; sq += hh[i] * hh[i]; }
    #pragma unroll
    for (int off = 16; off; off >>= 1) {
        s  += __shfl_xor_sync(0xFFFFFFFFu, s,  off);
        sq += __shfl_xor_sync(0xFFFFFFFFu, sq, off);
    }
    float mu  = s * (1.f / 256.f);
    float var = sq * (1.f / 256.f) - mu * mu;
    float rs  = rsqrtf(var + 1e-5f);

    float4 g1 = *(const float4*)(gamma + lane * 8);
    float4 g2 = *(const float4*)(gamma + lane * 8 + 4);
    float4 be1 = *(const float4*)(beta + lane * 8);
    float4 be2 = *(const float4*)(beta + lane * 8 + 4);

    float4 o1 = make_float4((hh[0] - mu) * rs * g1.x + be1.x,
                            (hh[1] - mu) * rs * g1.y + be1.y,
                            (hh[2] - mu) * rs * g1.z + be1.z,
                            (hh[3] - mu) * rs * g1.w + be1.w);
    float4 o2 = make_float4((hh[4] - mu) * rs * g2.x + be2.x,
                            (hh[5] - mu) * rs * g2.y + be2.y,
                            (hh[6] - mu) * rs * g2.z + be2.z,
                            (hh[7] - mu) * rs * g2.w + be2.w);
    *(float4*)(out + base)     = o1;
    *(float4*)(out + base + 4) = o2;
}

// ---------------------------------------------------------------------------
extern "C" void kernel_launch(void* const* d_in, const int* in_sizes, int n_in,
                              void* d_out, int out_size)
{
    const float* x     = (const float*)d_in[0];
    const float* Wq    = (const float*)d_in[1];
    const float* bq    = (const float*)d_in[2];
    const float* Wk    = (const float*)d_in[3];
    const float* bk    = (const float*)d_in[4];
    const float* Wv    = (const float*)d_in[5];
    const float* bv    = (const float*)d_in[6];
    const float* memk  = (const float*)d_in[7];
    const float* memv  = (const float*)d_in[8];
    const float* fcw   = (const float*)d_in[9];
    const float* fcb   = (const float*)d_in[10];
    const float* gamma = (const float*)d_in[11];
    const float* beta  = (const float*)d_in[12];
    const float* alpha = (const float*)d_in[13];
    float* out = (float*)d_out;

    float *qkv, *fc, *bias;
    __half *xh, *xl, *ah, *al, *wh;
    cudaGetSymbolAddress((void**)&qkv, g_qkv);
    cudaGetSymbolAddress((void**)&fc,  g_fc);
    cudaGetSymbolAddress((void**)&xh,  g_xh);
    cudaGetSymbolAddress((void**)&xl,  g_xl);
    cudaGetSymbolAddress((void**)&ah,  g_ah);
    cudaGetSymbolAddress((void**)&al,  g_al);
    cudaGetSymbolAddress((void**)&wh,  g_wh);
    cudaGetSymbolAddress((void**)&bias, g_bias);

    const int smem = NSTAGE * 3 * STG * 2;  // 73728 bytes
    cudaFuncSetAttribute(gemm_f16s, cudaFuncAttributeMaxDynamicSharedMemorySize, smem);

    // 0) split-convert inputs
    cvt_split<<<(unsigned)(XELEMS / 4 / 256), 256>>>(x, xh, xl, XELEMS);
    cvt_weights<<<256, 256>>>(Wq, Wk, Wv, fcw, bq, bk, bv, fcb);

    // 1) fused QKV projection
    {
        dim3 grid(6, ROWS / 128);
        gemm_f16s<<<grid, 256, smem>>>(xh, xl, wh, bias, qkv, 768);
    }
    // 2) attention per (b,n) -> hi/lo split output
    attn4_kernel<<<BNTOT, 256>>>(memk, memv, alpha, qkv, ah, al);

    // 3) FC projection
    {
        dim3 grid(2, ROWS / 128);
        gemm_f16s<<<grid, 256, smem>>>(ah, al, wh + 768 * 256, bias + 768, fc, 256);
    }
    // 4) residual + LayerNorm
    ln_kernel<<<(ROWS * 32 + 255) / 256, 256>>>(fc, x, gamma, beta, out);
}

// round 13
// speedup vs baseline: 1.8434x; 1.2439x over previous
#include <cuda_runtime.h>
#include <cuda_fp16.h>
#include <cstdint>

// Problem constants
#define BB 8
#define NN 2048
#define TT 12
#define DD 256
#define HH 8
#define DKK 32
#define MM 8

#define ROWS (BB*NN*TT)     // 196608
#define BNTOT (BB*NN)       // 16384
#define XELEMS ((size_t)ROWS * 256)

// Scratch (device globals: allocation-free kernel_launch)
__device__ float  g_qkv[(size_t)ROWS * 768];
__device__ float  g_fc [(size_t)ROWS * 256];
__device__ __half g_xh [XELEMS];               // x as f16
__device__ __half g_ah [XELEMS];               // attn out as f16
__device__ __half g_wh [1024 * 256];           // weights f16: [Wq;Wk;Wv;fc]
__device__ float  g_bias[1024];

// Triangular job decode tables (78 causal (t,s) pairs)
__constant__ unsigned char cJobT[78] = {
    0, 1,1, 2,2,2, 3,3,3,3, 4,4,4,4,4, 5,5,5,5,5,5,
    6,6,6,6,6,6,6, 7,7,7,7,7,7,7,7, 8,8,8,8,8,8,8,8,8,
    9,9,9,9,9,9,9,9,9,9, 10,10,10,10,10,10,10,10,10,10,10,
    11,11,11,11,11,11,11,11,11,11,11,11 };
__constant__ unsigned char cJobS[78] = {
    0, 0,1, 0,1,2, 0,1,2,3, 0,1,2,3,4, 0,1,2,3,4,5,
    0,1,2,3,4,5,6, 0,1,2,3,4,5,6,7, 0,1,2,3,4,5,6,7,8,
    0,1,2,3,4,5,6,7,8,9, 0,1,2,3,4,5,6,7,8,9,10,
    0,1,2,3,4,5,6,7,8,9,10,11 };

// ---------------------------------------------------------------------------
// f16 conversion helpers
// ---------------------------------------------------------------------------
__device__ __forceinline__ uint32_t pack2(__half a, __half b) {
    __half2 h = __halves2half2(a, b);
    return *(uint32_t*)&h;
}

__global__ __launch_bounds__(256) void cvt_half(
    const float* __restrict__ in, __half* __restrict__ hi, size_t n)
{
    size_t i = ((size_t)blockIdx.x * blockDim.x + threadIdx.x) * 4;
    if (i >= n) return;
    float4 v = *(const float4*)(in + i);
    *(uint2*)(hi + i) = make_uint2(
        pack2(__float2half_rn(v.x), __float2half_rn(v.y)),
        pack2(__float2half_rn(v.z), __float2half_rn(v.w)));
}

// weights: 4 matrices of 256x256 -> concatenated 1024x256 f16 plane; bias concat
__global__ __launch_bounds__(256) void cvt_weights(
    const float* __restrict__ Wq, const float* __restrict__ Wk,
    const float* __restrict__ Wv, const float* __restrict__ Wf,
    const float* __restrict__ bq, const float* __restrict__ bk,
    const float* __restrict__ bv, const float* __restrict__ bf)
{
    size_t i = ((size_t)blockIdx.x * blockDim.x + threadIdx.x) * 4;
    if (i < 4 * 65536) {
        int mat = (int)(i >> 16);
        size_t off = i & 65535;
        const float* W = (mat == 0) ? Wq : (mat == 1 ? Wk : (mat == 2 ? Wv : Wf));
        float4 v = *(const float4*)(W + off);
        *(uint2*)(g_wh + i) = make_uint2(
            pack2(__float2half_rn(v.x), __float2half_rn(v.y)),
            pack2(__float2half_rn(v.z), __float2half_rn(v.w)));
    }
    int t = blockIdx.x * blockDim.x + threadIdx.x;
    if (t < 256)        g_bias[t] = bq[t];
    else if (t < 512)   g_bias[t] = bk[t - 256];
    else if (t < 768)   g_bias[t] = bv[t - 512];
    else if (t < 1024)  g_bias[t] = bf[t - 768];
}

// ---------------------------------------------------------------------------
// Pure-f16 tensor-core GEMM (single term, fp32 accumulate).
// Block 128x128, 256 threads, 8 warps, warp tile 64x32, BK=16,
// 4-stage cp.async ring (2 planes/stage = 48 KB), one __syncthreads/stage.
// ---------------------------------------------------------------------------
#define ASTR 24
#define STG  (128 * ASTR)
#define NSTAGE 4

__device__ __forceinline__ void ldsm4(uint32_t* r, const __half* p) {
    uint32_t a = (uint32_t)__cvta_generic_to_shared(p);
    asm volatile("ldmatrix.sync.aligned.m8n8.x4.shared.b16 {%0,%1,%2,%3}, [%4];"
                 : "=r"(r[0]), "=r"(r[1]), "=r"(r[2]), "=r"(r[3]) : "r"(a));
}
__device__ __forceinline__ void mma16816(float* d, const uint32_t* a, const uint32_t* b) {
    asm volatile("mma.sync.aligned.m16n8k16.row.col.f32.f16.f16.f32 "
        "{%0,%1,%2,%3}, {%4,%5,%6,%7}, {%8,%9}, {%0,%1,%2,%3};"
        : "+f"(d[0]), "+f"(d[1]), "+f"(d[2]), "+f"(d[3])
        : "r"(a[0]), "r"(a[1]), "r"(a[2]), "r"(a[3]), "r"(b[0]), "r"(b[1]));
}
__device__ __forceinline__ void cpa16(__half* dst, const __half* src) {
    uint32_t d = (uint32_t)__cvta_generic_to_shared(dst);
    asm volatile("cp.async.cg.shared.global [%0], [%1], 16;" :: "r"(d), "l"(src));
}

__global__ __launch_bounds__(256, 2) void gemm_f16s(
    const __half* __restrict__ Ah,
    const __half* __restrict__ Wh,
    const float* __restrict__ bias,
    float* __restrict__ C, int ldc)
{
    extern __shared__ __half sm[];   // [NSTAGE][2 planes][STG] = 48 KB

    const int tid  = threadIdx.x;
    const int m0   = blockIdx.y * 128;
    const int n0   = blockIdx.x * 128;
    const int wid  = tid >> 5;
    const int lane = tid & 31;
    const int WM = (wid & 1) * 64;
    const int WN = (wid >> 1) * 32;

    const int lrow = tid >> 1;
    const int lch  = (tid & 1) * 8;
    const size_t aoff = (size_t)(m0 + lrow) * 256 + lch;
    const size_t boff = (size_t)(n0 + lrow) * 256 + lch;
    const int sdst = lrow * ASTR + lch;

    float acc[4][4][4];
    #pragma unroll
    for (int i = 0; i < 4; i++)
        #pragma unroll
        for (int j = 0; j < 4; j++)
            #pragma unroll
            for (int e = 0; e < 4; e++) acc[i][j][e] = 0.f;

    auto load_stage = [&](int k0, int buf) {
        __half* b = sm + buf * 2 * STG;
        cpa16(b + 0 * STG + sdst, Ah + aoff + k0);
        cpa16(b + 1 * STG + sdst, Wh + boff + k0);
        asm volatile("cp.async.commit_group;");
    };

    load_stage(0, 0);
    load_stage(16, 1);
    load_stage(32, 2);

    for (int s = 0; s < 16; s++) {
        if (s <= 13)      asm volatile("cp.async.wait_group 2;");
        else if (s == 14) asm volatile("cp.async.wait_group 1;");
        else              asm volatile("cp.async.wait_group 0;");
        __syncthreads();

        if (s <= 12) load_stage((s + 3) * 16, (s + 3) & 3);

        const __half* bAh = sm + (s & 3) * 2 * STG;
        const __half* bBh = bAh + STG;

        uint32_t ah[4][4], bh[2][4];
        const int ar = WM + (lane & 15);
        const int ac = (lane & 16) >> 1;
        #pragma unroll
        for (int i = 0; i < 4; i++) {
            ldsm4(ah[i], bAh + (ar + i * 16) * ASTR + ac);
        }
        const int br = WN + (lane & 7) + ((lane & 16) >> 1);
        const int bc = lane & 8;
        #pragma unroll
        for (int j = 0; j < 2; j++) {
            ldsm4(bh[j], bBh + (br + j * 16) * ASTR + bc);
        }
        #pragma unroll
        for (int i = 0; i < 4; i++) {
            #pragma unroll
            for (int jj = 0; jj < 4; jj++) {
                const uint32_t* bhp = &bh[jj >> 1][(jj & 1) * 2];
                mma16816(acc[i][jj], ah[i], bhp);
            }
        }
    }

    const int cr = lane >> 2;
    const int cc = (lane & 3) * 2;
    #pragma unroll
    for (int jj = 0; jj < 4; jj++) {
        int coll = WN + jj * 8 + cc;
        float bv0 = bias[n0 + coll];
        float bv1 = bias[n0 + coll + 1];
        #pragma unroll
        for (int i = 0; i < 4; i++) {
            int r0 = m0 + WM + i * 16 + cr;
            *(float2*)(C + (size_t)r0 * ldc + n0 + coll) =
                make_float2(acc[i][jj][0] + bv0, acc[i][jj][1] + bv1);
            *(float2*)(C + (size_t)(r0 + 8) * ldc + n0 + coll) =
                make_float2(acc[i][jj][2] + bv0, acc[i][jj][3] + bv1);
        }
    }
}

// ---------------------------------------------------------------------------
// Attention v4 (R11 structure): group-of-4 cooperative dots; f16 output.
// ---------------------------------------------------------------------------
__global__ __launch_bounds__(256) void attn4_kernel(
    const float* __restrict__ memk,
    const float* __restrict__ memv,
    const float* __restrict__ alpha,
    const float* __restrict__ QKV,
    __half* __restrict__ Oh)
{
    __shared__ float sQ [HH][TT][36];
    __shared__ float sK [HH][TT][36];
    __shared__ float sMK[HH][MM][36];
    __shared__ float sS [HH][TT][13];
    __shared__ float sL [HH][TT][9];

    const int bn   = blockIdx.x;
    const int h    = threadIdx.x >> 5;
    const int lane = threadIdx.x & 31;
    const int grp  = lane >> 2;
    const int sub  = lane & 3;
    const size_t rb = (size_t)bn * TT * 768;
    const float scale = 0.1767766952966369f;

    float v[TT];
    #pragma unroll
    for (int t = 0; t < TT; t++) {
        sQ[h][t][lane] = QKV[rb + (size_t)t * 768 +       h * 32 + lane];
        sK[h][t][lane] = QKV[rb + (size_t)t * 768 + 256 + h * 32 + lane];
        v[t]           = QKV[rb + (size_t)t * 768 + 512 + h * 32 + lane];
    }
    {
        int mr = lane >> 2, mc = (lane & 3) * 8;
        const float* src = memk + ((h << 3) + mr) * 32 + mc;
        #pragma unroll
        for (int e = 0; e < 8; e++) sMK[h][mr][mc + e] = src[e];
    }
    float mv[MM];
    #pragma unroll
    for (int m = 0; m < MM; m++) mv[m] = memv[((h << 3) + m) * 32 + lane];
    __syncwarp();

    #pragma unroll 1
    for (int it = 0; it < 22; it++) {
        int j = it * 8 + grp;
        int jc = (j < 174) ? j : 173;
        const float4 *q4, *k4;
        int t, s;
        bool causal;
        if (jc < 78) {
            t = cJobT[jc]; s = cJobS[jc];
            causal = true;
            q4 = (const float4*)sQ[h][t];
            k4 = (const float4*)sK[h][s];
        } else {
            int jm = jc - 78;
            t = jm >> 3; s = jm & 7;
            causal = false;
            q4 = (const float4*)sQ[h][t];
            k4 = (const float4*)sMK[h][s];
        }
        float4 qa = q4[sub * 2], qb = q4[sub * 2 + 1];
        float4 ka = k4[sub * 2], kb = k4[sub * 2 + 1];
        float p0 = qa.x * ka.x + qa.y * ka.y + qa.z * ka.z + qa.w * ka.w;
        float p1 = qb.x * kb.x + qb.y * kb.y + qb.z * kb.z + qb.w * kb.w;
        float p = p0 + p1;
        p += __shfl_xor_sync(0xFFFFFFFFu, p, 1);
        p += __shfl_xor_sync(0xFFFFFFFFu, p, 2);
        if (sub == 0 && j < 174) {
            if (causal) sS[h][t][s] = p * scale;
            else        sL[h][t][s] = p * scale;
        }
    }
    __syncwarp();

    if (lane < TT) {
        int t = lane;
        float mx = -1e30f;
        for (int s = 0; s <= t; s++) mx = fmaxf(mx, sS[h][t][s]);
        float sum = 0.f;
        for (int s = 0; s <= t; s++) { float e = __expf(sS[h][t][s] - mx); sS[h][t][s] = e; sum += e; }
        float inv = 1.f / sum;
        for (int s = 0; s <= t; s++) sS[h][t][s] *= inv;

        mx = -1e30f;
        #pragma unroll
        for (int m = 0; m < MM; m++) mx = fmaxf(mx, sL[h][t][m]);
        sum = 0.f;
        #pragma unroll
        for (int m = 0; m < MM; m++) { float e = __expf(sL[h][t][m] - mx); sL[h][t][m] = e; sum += e; }
        inv = 1.f / sum;
        #pragma unroll
        for (int m = 0; m < MM; m++) sL[h][t][m] *= inv;
    }
    __syncwarp();

    const float wl = 1.f / (1.f + __expf(-alpha[0]));
    const float wt = 1.f - wl;

    #pragma unroll
    for (int t = 0; t < TT; t++) {
        float o0 = 0.f, o1 = 0.f;
        for (int s = 0; s + 1 <= t; s += 2) {
            o0 = fmaf(sS[h][t][s],     v[s],     o0);
            o1 = fmaf(sS[h][t][s + 1], v[s + 1], o1);
        }
        if ((t & 1) == 0) o0 = fmaf(sS[h][t][t], v[t], o0);
        float l0 = 0.f, l1 = 0.f;
        #pragma unroll
        for (int m = 0; m < MM; m += 2) {
            l0 = fmaf(sL[h][t][m],     mv[m],     l0);
            l1 = fmaf(sL[h][t][m + 1], mv[m + 1], l1);
        }
        float o = (o0 + o1) * wt + (l0 + l1) * wl;
        size_t oi = (size_t)bn * TT * 256 + (size_t)t * 256 + h * 32 + lane;
        Oh[oi] = __float2half_rn(o);
    }
}

// ---------------------------------------------------------------------------
// Residual + LayerNorm: one warp per row of 256.
// ---------------------------------------------------------------------------
__global__ __launch_bounds__(256) void ln_kernel(
    const float* __restrict__ Y, const float* __restrict__ X,
    const float* __restrict__ gamma, const float* __restrict__ beta,
    float* __restrict__ out)
{
    int gw   = (blockIdx.x * blockDim.x + threadIdx.x) >> 5;
    int lane = threadIdx.x & 31;
    if (gw >= ROWS) return;
    size_t base = (size_t)gw * 256 + lane * 8;

    float4 y1 = *(const float4*)(Y + base);
    float4 y2 = *(const float4*)(Y + base + 4);
    float4 x1 = *(const float4*)(X + base);
    float4 x2 = *(const float4*)(X + base + 4);
    float hh[8] = { y1.x + x1.x, y1.y + x1.y, y1.z + x1.z, y1.w + x1.w,
                    y2.x + x2.x, y2.y + x2.y, y2.z + x2.z, y2.w + x2.w };

    float s = 0.f, sq = 0.f;
    #pragma unroll
    for (int i = 0; i < 8; i++) { s += hh[i]; sq += hh[i] * hh[i]; }
    #pragma unroll
    for (int off = 16; off; off >>= 1) {
        s  += __shfl_xor_sync(0xFFFFFFFFu, s,  off);
        sq += __shfl_xor_sync(0xFFFFFFFFu, sq, off);
    }
    float mu  = s * (1.f / 256.f);
    float var = sq * (1.f / 256.f) - mu * mu;
    float rs  = rsqrtf(var + 1e-5f);

    float4 g1 = *(const float4*)(gamma + lane * 8);
    float4 g2 = *(const float4*)(gamma + lane * 8 + 4);
    float4 be1 = *(const float4*)(beta + lane * 8);
    float4 be2 = *(const float4*)(beta + lane * 8 + 4);

    float4 o1 = make_float4((hh[0] - mu) * rs * g1.x + be1.x,
                            (hh[1] - mu) * rs * g1.y + be1.y,
                            (hh[2] - mu) * rs * g1.z + be1.z,
                            (hh[3] - mu) * rs * g1.w + be1.w);
    float4 o2 = make_float4((hh[4] - mu) * rs * g2.x + be2.x,
                            (hh[5] - mu) * rs * g2.y + be2.y,
                            (hh[6] - mu) * rs * g2.z + be2.z,
                            (hh[7] - mu) * rs * g2.w + be2.w);
    *(float4*)(out + base)     = o1;
    *(float4*)(out + base + 4) = o2;
}

// ---------------------------------------------------------------------------
extern "C" void kernel_launch(void* const* d_in, const int* in_sizes, int n_in,
                              void* d_out, int out_size)
{
    const float* x     = (const float*)d_in[0];
    const float* Wq    = (const float*)d_in[1];
    const float* bq    = (const float*)d_in[2];
    const float* Wk    = (const float*)d_in[3];
    const float* bk    = (const float*)d_in[4];
    const float* Wv    = (const float*)d_in[5];
    const float* bv    = (const float*)d_in[6];
    const float* memk  = (const float*)d_in[7];
    const float* memv  = (const float*)d_in[8];
    const float* fcw   = (const float*)d_in[9];
    const float* fcb   = (const float*)d_in[10];
    const float* gamma = (const float*)d_in[11];
    const float* beta  = (const float*)d_in[12];
    const float* alpha = (const float*)d_in[13];
    float* out = (float*)d_out;

    float *qkv, *fc, *bias;
    __half *xh, *ah, *wh;
    cudaGetSymbolAddress((void**)&qkv, g_qkv);
    cudaGetSymbolAddress((void**)&fc,  g_fc);
    cudaGetSymbolAddress((void**)&xh,  g_xh);
    cudaGetSymbolAddress((void**)&ah,  g_ah);
    cudaGetSymbolAddress((void**)&wh,  g_wh);
    cudaGetSymbolAddress((void**)&bias, g_bias);

    const int smem = NSTAGE * 2 * STG * 2;  // 49152 bytes
    cudaFuncSetAttribute(gemm_f16s, cudaFuncAttributeMaxDynamicSharedMemorySize, smem);

    // 0) f16 conversion of inputs
    cvt_half<<<(unsigned)(XELEMS / 4 / 256), 256>>>(x, xh, XELEMS);
    cvt_weights<<<256, 256>>>(Wq, Wk, Wv, fcw, bq, bk, bv, fcb);

    // 1) fused QKV projection
    {
        dim3 grid(6, ROWS / 128);
        gemm_f16s<<<grid, 256, smem>>>(xh, wh, bias, qkv, 768);
    }
    // 2) attention per (b,n) -> f16 output
    attn4_kernel<<<BNTOT, 256>>>(memk, memv, alpha, qkv, ah);

    // 3) FC projection
    {
        dim3 grid(2, ROWS / 128);
        gemm_f16s<<<grid, 256, smem>>>(ah, wh + 768 * 256, bias + 768, fc, 256);
    }
    // 4) residual + LayerNorm
    ln_kernel<<<(ROWS * 32 + 255) / 256, 256>>>(fc, x, gamma, beta, out);
}